// round 1
// baseline (speedup 1.0000x reference)
#include <cuda_runtime.h>
#include <cuda_bf16.h>
#include <cmath>

// Problem constants
#define BATCH 2
#define SEQ   2048
#define EMB   1024
#define HEADS 16
#define HDIM  64
#define MROWS (BATCH*SEQ)   // 4096

// Scratch (device globals; no allocation allowed)
__device__ float g_q[BATCH*HEADS*SEQ*HDIM];     // (B,H,T,D)
__device__ float g_k[BATCH*HEADS*SEQ*HDIM];
__device__ float g_v[BATCH*HEADS*SEQ*HDIM];
__device__ float g_attn[BATCH*SEQ*EMB];         // (B,T,C)

// ---------------------------------------------------------------------------
// GEMM: out[m][n] = sum_k A[m][k] * W[n][k] + bias[n]
// BM=BN=128, BK=16, 256 threads, 8x8 per thread.
// SCATTER=true writes into (B,H,T,D) layout; false writes row-major [m][n].
// ---------------------------------------------------------------------------
template<bool SCATTER>
__device__ __forceinline__ void gemm_body(
    const float* __restrict__ A, const float* __restrict__ W,
    const float* __restrict__ bias, float* __restrict__ dst)
{
    __shared__ float As[16][128];
    __shared__ float Bs[16][128];

    const int tid = threadIdx.x;
    const int tx = tid & 15;
    const int ty = tid >> 4;
    const int m0 = blockIdx.x * 128;
    const int n0 = blockIdx.y * 128;

    const int lr = tid >> 2;          // 0..63
    const int lk = (tid & 3) * 4;     // 0,4,8,12

    float acc[8][8];
#pragma unroll
    for (int i = 0; i < 8; i++)
#pragma unroll
        for (int j = 0; j < 8; j++) acc[i][j] = 0.f;

    for (int k0 = 0; k0 < EMB; k0 += 16) {
        float4 a0 = *(const float4*)&A[(m0 + lr     ) * EMB + k0 + lk];
        float4 a1 = *(const float4*)&A[(m0 + lr + 64) * EMB + k0 + lk];
        float4 w0 = *(const float4*)&W[(n0 + lr     ) * EMB + k0 + lk];
        float4 w1 = *(const float4*)&W[(n0 + lr + 64) * EMB + k0 + lk];

        __syncthreads();   // previous iteration's readers done
        As[lk+0][lr] = a0.x; As[lk+1][lr] = a0.y; As[lk+2][lr] = a0.z; As[lk+3][lr] = a0.w;
        As[lk+0][lr+64] = a1.x; As[lk+1][lr+64] = a1.y; As[lk+2][lr+64] = a1.z; As[lk+3][lr+64] = a1.w;
        Bs[lk+0][lr] = w0.x; Bs[lk+1][lr] = w0.y; Bs[lk+2][lr] = w0.z; Bs[lk+3][lr] = w0.w;
        Bs[lk+0][lr+64] = w1.x; Bs[lk+1][lr+64] = w1.y; Bs[lk+2][lr+64] = w1.z; Bs[lk+3][lr+64] = w1.w;
        __syncthreads();

#pragma unroll
        for (int k = 0; k < 16; k++) {
            float4 av0 = *(const float4*)&As[k][4*ty];
            float4 av1 = *(const float4*)&As[k][4*ty + 64];
            float4 bv0 = *(const float4*)&Bs[k][4*tx];
            float4 bv1 = *(const float4*)&Bs[k][4*tx + 64];
            float av[8] = {av0.x, av0.y, av0.z, av0.w, av1.x, av1.y, av1.z, av1.w};
            float bv[8] = {bv0.x, bv0.y, bv0.z, bv0.w, bv1.x, bv1.y, bv1.z, bv1.w};
#pragma unroll
            for (int i = 0; i < 8; i++)
#pragma unroll
                for (int j = 0; j < 8; j++)
                    acc[i][j] = fmaf(av[i], bv[j], acc[i][j]);
        }
    }

    // Epilogue
#pragma unroll
    for (int i = 0; i < 8; i++) {
        const int gm = m0 + ((i < 4) ? (4*ty + i) : (60 + 4*ty + i)); // i>=4: 64+4ty+(i-4)
#pragma unroll
        for (int half = 0; half < 2; half++) {
            const int gn = n0 + half * 64 + 4 * tx;
            float4 bb = *(const float4*)&bias[gn];
            float4 r;
            r.x = acc[i][half*4+0] + bb.x;
            r.y = acc[i][half*4+1] + bb.y;
            r.z = acc[i][half*4+2] + bb.z;
            r.w = acc[i][half*4+3] + bb.w;
            if (SCATTER) {
                const int b = gm >> 11;       // /2048
                const int t = gm & 2047;
                const int h = gn >> 6;        // /64
                const int d = gn & 63;
                *(float4*)&dst[(((b*HEADS + h) * SEQ) + t) * HDIM + d] = r;
            } else {
                *(float4*)&dst[gm * EMB + gn] = r;
            }
        }
    }
}

__global__ void __launch_bounds__(256) qkv_kernel(
    const float* __restrict__ x,
    const float* __restrict__ Wq, const float* __restrict__ bq,
    const float* __restrict__ Wk, const float* __restrict__ bk,
    const float* __restrict__ Wv, const float* __restrict__ bv)
{
    const int z = blockIdx.z;
    const float* W    = (z == 0) ? Wq : (z == 1) ? Wk : Wv;
    const float* bias = (z == 0) ? bq : (z == 1) ? bk : bv;
    float* dst        = (z == 0) ? g_q : (z == 1) ? g_k : g_v;
    gemm_body<true>(x, W, bias, dst);
}

__global__ void __launch_bounds__(256) proj_kernel(
    const float* __restrict__ Wo, const float* __restrict__ bo,
    float* __restrict__ out)
{
    gemm_body<false>(g_attn, Wo, bo, out);
}

// ---------------------------------------------------------------------------
// Causal flash attention.
// Block: one (b,h) pair x one 64-query tile. 256 threads (16x16), 4x4/thread.
// Dynamic smem: Qs[64][64] d-major, Ks[64][64] d-major, Vs[64][64] row-major,
//               Ss[64][65], row_m/row_l/row_a[64].
// ---------------------------------------------------------------------------
#define ATTN_SMEM_FLOATS (4096*3 + 64*65 + 3*64)
#define ATTN_SMEM_BYTES  (ATTN_SMEM_FLOATS * 4)

__global__ void __launch_bounds__(256) attn_kernel()
{
    extern __shared__ float sm[];
    float* Qs = sm;                 // [d][m]
    float* Ks = sm + 4096;          // [d][n]
    float* Vs = sm + 8192;          // [j][d]
    float* Ss = sm + 12288;         // [64][65]
    float* row_m = Ss + 64*65;
    float* row_l = row_m + 64;
    float* row_a = row_l + 64;

    const int tid = threadIdx.x;
    const int tx = tid & 15;
    const int ty = tid >> 4;
    const int qt = blockIdx.x;      // query tile (0..31)
    const int bh = blockIdx.y;      // b*HEADS + h (0..31)

    const float* qptr = g_q + (size_t)bh * SEQ * HDIM;
    const float* kptr = g_k + (size_t)bh * SEQ * HDIM;
    const float* vptr = g_v + (size_t)bh * SEQ * HDIM;

    // Load Q tile transposed: Qs[d][m]
    {
        const int m  = tid >> 4;           // 0..15
        const int d0 = (tid & 15) * 4;
#pragma unroll
        for (int mm = m; mm < 64; mm += 16) {
            float4 qv = *(const float4*)&qptr[(qt*64 + mm) * HDIM + d0];
            Qs[(d0+0)*64 + mm] = qv.x;
            Qs[(d0+1)*64 + mm] = qv.y;
            Qs[(d0+2)*64 + mm] = qv.z;
            Qs[(d0+3)*64 + mm] = qv.w;
        }
    }
    if (tid < 64) { row_m[tid] = -INFINITY; row_l[tid] = 0.f; }

    float acc[4][4];
#pragma unroll
    for (int a = 0; a < 4; a++)
#pragma unroll
        for (int b = 0; b < 4; b++) acc[a][b] = 0.f;

    const float LOG2E = 1.4426950408889634f;
    const float scale = 0.125f;   // 1/sqrt(64)

    for (int kt = 0; kt <= qt; kt++) {
        __syncthreads();
        // Load K (transposed) and V (direct)
        {
            const int m  = tid >> 4;
            const int d0 = (tid & 15) * 4;
#pragma unroll
            for (int mm = m; mm < 64; mm += 16) {
                float4 kv = *(const float4*)&kptr[(kt*64 + mm) * HDIM + d0];
                Ks[(d0+0)*64 + mm] = kv.x;
                Ks[(d0+1)*64 + mm] = kv.y;
                Ks[(d0+2)*64 + mm] = kv.z;
                Ks[(d0+3)*64 + mm] = kv.w;
                float4 vv = *(const float4*)&vptr[(kt*64 + mm) * HDIM + d0];
                *(float4*)&Vs[mm*64 + d0] = vv;
            }
        }
        __syncthreads();

        // S = Q K^T (4x4 per thread)
        float s[4][4];
#pragma unroll
        for (int a = 0; a < 4; a++)
#pragma unroll
            for (int b = 0; b < 4; b++) s[a][b] = 0.f;

#pragma unroll 16
        for (int d = 0; d < 64; d++) {
            float4 qv = *(const float4*)&Qs[d*64 + 4*ty];
            float4 kv = *(const float4*)&Ks[d*64 + 4*tx];
            float qa[4] = {qv.x, qv.y, qv.z, qv.w};
            float kb[4] = {kv.x, kv.y, kv.z, kv.w};
#pragma unroll
            for (int a = 0; a < 4; a++)
#pragma unroll
                for (int b = 0; b < 4; b++)
                    s[a][b] = fmaf(qa[a], kb[b], s[a][b]);
        }

        const bool diag = (kt == qt);
#pragma unroll
        for (int a = 0; a < 4; a++)
#pragma unroll
            for (int b = 0; b < 4; b++) {
                float v = s[a][b] * scale;
                if (diag && (4*tx + b > 4*ty + a)) v = -1e30f;
                Ss[(4*ty + a) * 65 + 4*tx + b] = v;
            }
        __syncthreads();

        // Online softmax: 4 threads per row, 16 cols each
        {
            const int r  = tid >> 2;
            const int c0 = (tid & 3) * 16;
            float mx = -INFINITY;
#pragma unroll
            for (int c = 0; c < 16; c++) mx = fmaxf(mx, Ss[r*65 + c0 + c]);
            mx = fmaxf(mx, __shfl_xor_sync(0xffffffffu, mx, 1));
            mx = fmaxf(mx, __shfl_xor_sync(0xffffffffu, mx, 2));
            const float m_old = row_m[r];
            const float m_new = fmaxf(m_old, mx);
            float sum = 0.f;
#pragma unroll
            for (int c = 0; c < 16; c++) {
                float p = exp2f((Ss[r*65 + c0 + c] - m_new) * LOG2E);
                Ss[r*65 + c0 + c] = p;
                sum += p;
            }
            sum += __shfl_xor_sync(0xffffffffu, sum, 1);
            sum += __shfl_xor_sync(0xffffffffu, sum, 2);
            if ((tid & 3) == 0) {
                float alpha = exp2f((m_old - m_new) * LOG2E);
                row_a[r] = alpha;
                row_m[r] = m_new;
                row_l[r] = row_l[r] * alpha + sum;
            }
        }
        __syncthreads();

        // O = O*alpha + P V
        float al[4];
#pragma unroll
        for (int a = 0; a < 4; a++) al[a] = row_a[4*ty + a];
#pragma unroll
        for (int a = 0; a < 4; a++)
#pragma unroll
            for (int b = 0; b < 4; b++) acc[a][b] *= al[a];

#pragma unroll 8
        for (int j = 0; j < 64; j++) {
            float4 vv = *(const float4*)&Vs[j*64 + 4*tx];
            float p0 = Ss[(4*ty + 0)*65 + j];
            float p1 = Ss[(4*ty + 1)*65 + j];
            float p2 = Ss[(4*ty + 2)*65 + j];
            float p3 = Ss[(4*ty + 3)*65 + j];
            acc[0][0] = fmaf(p0, vv.x, acc[0][0]); acc[0][1] = fmaf(p0, vv.y, acc[0][1]);
            acc[0][2] = fmaf(p0, vv.z, acc[0][2]); acc[0][3] = fmaf(p0, vv.w, acc[0][3]);
            acc[1][0] = fmaf(p1, vv.x, acc[1][0]); acc[1][1] = fmaf(p1, vv.y, acc[1][1]);
            acc[1][2] = fmaf(p1, vv.z, acc[1][2]); acc[1][3] = fmaf(p1, vv.w, acc[1][3]);
            acc[2][0] = fmaf(p2, vv.x, acc[2][0]); acc[2][1] = fmaf(p2, vv.y, acc[2][1]);
            acc[2][2] = fmaf(p2, vv.z, acc[2][2]); acc[2][3] = fmaf(p2, vv.w, acc[2][3]);
            acc[3][0] = fmaf(p3, vv.x, acc[3][0]); acc[3][1] = fmaf(p3, vv.y, acc[3][1]);
            acc[3][2] = fmaf(p3, vv.z, acc[3][2]); acc[3][3] = fmaf(p3, vv.w, acc[3][3]);
        }
    }

    // Finalize and write to (B,T,C)
    const int b = bh >> 4;
    const int h = bh & 15;
#pragma unroll
    for (int a = 0; a < 4; a++) {
        const float inv = 1.0f / row_l[4*ty + a];
        const int t = qt*64 + 4*ty + a;
        float4 r;
        r.x = acc[a][0] * inv; r.y = acc[a][1] * inv;
        r.z = acc[a][2] * inv; r.w = acc[a][3] * inv;
        *(float4*)&g_attn[((size_t)(b*SEQ + t)) * EMB + h*HDIM + 4*tx] = r;
    }
}

// ---------------------------------------------------------------------------
extern "C" void kernel_launch(void* const* d_in, const int* in_sizes, int n_in,
                              void* d_out, int out_size)
{
    const float* x   = (const float*)d_in[0];
    const float* W_q = (const float*)d_in[1];
    const float* b_q = (const float*)d_in[2];
    const float* W_k = (const float*)d_in[3];
    const float* b_k = (const float*)d_in[4];
    const float* W_v = (const float*)d_in[5];
    const float* b_v = (const float*)d_in[6];
    const float* W_o = (const float*)d_in[7];
    const float* b_o = (const float*)d_in[8];
    float* out = (float*)d_out;

    static bool attr_set = false;
    if (!attr_set) {
        cudaFuncSetAttribute(attn_kernel,
                             cudaFuncAttributeMaxDynamicSharedMemorySize,
                             ATTN_SMEM_BYTES);
        attr_set = true;
    }

    dim3 gqkv(MROWS/128, EMB/128, 3);
    qkv_kernel<<<gqkv, 256>>>(x, W_q, b_q, W_k, b_k, W_v, b_v);

    dim3 gattn(SEQ/64, BATCH*HEADS);
    attn_kernel<<<gattn, 256, ATTN_SMEM_BYTES>>>();

    dim3 gproj(MROWS/128, EMB/128);
    proj_kernel<<<gproj, 256>>>(W_o, b_o, out);
}

// round 3
// speedup vs baseline: 1.2965x; 1.2965x over previous
#include <cuda_runtime.h>
#include <cuda_bf16.h>
#include <cstdint>
#include <cmath>

// Problem constants
#define BATCH 2
#define SEQ   2048
#define EMB   1024
#define HEADS 16
#define HDIM  64
#define MROWS (BATCH*SEQ)   // 4096

// Scratch (device globals; no allocation allowed)
__device__ float g_q[BATCH*HEADS*SEQ*HDIM];     // (B,H,T,D)
__device__ float g_k[BATCH*HEADS*SEQ*HDIM];
__device__ float g_v[BATCH*HEADS*SEQ*HDIM];
__device__ float g_attn[MROWS*EMB];             // (B,T,C)
__device__ __nv_bfloat16 g_xh[MROWS*EMB];
__device__ __nv_bfloat16 g_xl[MROWS*EMB];
__device__ __nv_bfloat16 g_wh[4*EMB*EMB];
__device__ __nv_bfloat16 g_wl[4*EMB*EMB];
__device__ __nv_bfloat16 g_ah[MROWS*EMB];
__device__ __nv_bfloat16 g_al[MROWS*EMB];

// ---------------------------------------------------------------------------
// PTX helpers (family-level: sm_80+ instructions only)
// ---------------------------------------------------------------------------
__device__ __forceinline__ uint32_t smem_u32(const void* p) {
    uint32_t a;
    asm("{ .reg .u64 t; cvta.to.shared.u64 t, %1; cvt.u32.u64 %0, t; }" : "=r"(a) : "l"(p));
    return a;
}
__device__ __forceinline__ void cp_async16(uint32_t dst, const void* src) {
    asm volatile("cp.async.cg.shared.global [%0], [%1], 16;" :: "r"(dst), "l"(src));
}
__device__ __forceinline__ void cp_commit() {
    asm volatile("cp.async.commit_group;" ::: "memory");
}
template<int N>
__device__ __forceinline__ void cp_wait() {
    asm volatile("cp.async.wait_group %0;" :: "n"(N) : "memory");
}
__device__ __forceinline__ void ldsm_x4(uint32_t* r, uint32_t addr) {
    asm volatile("ldmatrix.sync.aligned.m8n8.x4.shared.b16 {%0,%1,%2,%3}, [%4];"
                 : "=r"(r[0]), "=r"(r[1]), "=r"(r[2]), "=r"(r[3]) : "r"(addr));
}
__device__ __forceinline__ void ldsm_x2(uint32_t* r, uint32_t addr) {
    asm volatile("ldmatrix.sync.aligned.m8n8.x2.shared.b16 {%0,%1}, [%2];"
                 : "=r"(r[0]), "=r"(r[1]) : "r"(addr));
}
__device__ __forceinline__ void mma16816(float* c, const uint32_t* a, const uint32_t* b) {
    asm volatile(
        "mma.sync.aligned.m16n8k16.row.col.f32.bf16.bf16.f32 "
        "{%0,%1,%2,%3}, {%4,%5,%6,%7}, {%8,%9}, {%0,%1,%2,%3};"
        : "+f"(c[0]), "+f"(c[1]), "+f"(c[2]), "+f"(c[3])
        : "r"(a[0]), "r"(a[1]), "r"(a[2]), "r"(a[3]), "r"(b[0]), "r"(b[1]));
}

// ---------------------------------------------------------------------------
// fp32 -> (bf16 hi, bf16 lo) split
// ---------------------------------------------------------------------------
__global__ void __launch_bounds__(256) convert_split_kernel(
    const float* __restrict__ src,
    __nv_bfloat16* __restrict__ hi, __nv_bfloat16* __restrict__ lo, int n4)
{
    int i = blockIdx.x * blockDim.x + threadIdx.x;
    if (i >= n4) return;
    float4 v = ((const float4*)src)[i];
    __nv_bfloat16 h0 = __float2bfloat16(v.x);
    __nv_bfloat16 h1 = __float2bfloat16(v.y);
    __nv_bfloat16 h2 = __float2bfloat16(v.z);
    __nv_bfloat16 h3 = __float2bfloat16(v.w);
    __nv_bfloat16 l0 = __float2bfloat16(v.x - __bfloat162float(h0));
    __nv_bfloat16 l1 = __float2bfloat16(v.y - __bfloat162float(h1));
    __nv_bfloat16 l2 = __float2bfloat16(v.z - __bfloat162float(h2));
    __nv_bfloat16 l3 = __float2bfloat16(v.w - __bfloat162float(h3));
    __nv_bfloat162 hv0; hv0.x = h0; hv0.y = h1;
    __nv_bfloat162 hv1; hv1.x = h2; hv1.y = h3;
    __nv_bfloat162 lv0; lv0.x = l0; lv0.y = l1;
    __nv_bfloat162 lv1; lv1.x = l2; lv1.y = l3;
    ((__nv_bfloat162*)hi)[2*i]   = hv0;
    ((__nv_bfloat162*)hi)[2*i+1] = hv1;
    ((__nv_bfloat162*)lo)[2*i]   = lv0;
    ((__nv_bfloat162*)lo)[2*i+1] = lv1;
}

// ---------------------------------------------------------------------------
// HMMA GEMM: out[m][n] = sum_k A[m][k]*W[n][k] + bias[n], 3x-bf16 split.
// CTA: 128x128 tile, 256 threads, 8 warps (4x2), warp tile 32x64.
// K chunks of 32, 3-stage cp.async pipeline, padded smem stride 40 bf16.
// ---------------------------------------------------------------------------
#define BK 32
#define LDT 40                         // bf16 elems per smem row (80 B)
#define TILE_SM (128*LDT)              // bf16 per tile
#define STAGE_SM (4*TILE_SM)           // Ah, Al, Bh, Bl
#define STAGES 3
#define NCH (EMB/BK)                   // 32
#define GSMEM_BYTES (STAGES*STAGE_SM*2)

template<bool SCATTER>
__device__ __forceinline__ void hgemm_body(
    const __nv_bfloat16* __restrict__ Ah, const __nv_bfloat16* __restrict__ Al,
    const __nv_bfloat16* __restrict__ Bh, const __nv_bfloat16* __restrict__ Bl,
    const float* __restrict__ bias, float* __restrict__ dst)
{
    extern __shared__ __nv_bfloat16 smb[];
    const uint32_t sm0 = smem_u32(smb);

    const int tid  = threadIdx.x;
    const int wid  = tid >> 5;
    const int lane = tid & 31;
    const int m0 = blockIdx.x * 128;
    const int n0 = blockIdx.y * 128;
    const int warp_m = (wid >> 1) * 32;
    const int warp_n = (wid & 1) * 64;

    const __nv_bfloat16* gsrc[4];
    gsrc[0] = Ah + (size_t)m0 * EMB;
    gsrc[1] = Al + (size_t)m0 * EMB;
    gsrc[2] = Bh + (size_t)n0 * EMB;
    gsrc[3] = Bl + (size_t)n0 * EMB;

    // --- async chunk loader: 4 tiles x 128 rows x 64B, 2 x 16B per thread/tile
    auto load_chunk = [&](int stage, int kc) {
        const uint32_t sb = sm0 + (uint32_t)stage * STAGE_SM * 2;
#pragma unroll
        for (int t4 = 0; t4 < 4; t4++) {
#pragma unroll
            for (int e = 0; e < 2; e++) {
                const int idx = tid * 2 + e;      // 0..511
                const int row = idx >> 2;
                const int c4  = idx & 3;
                const void* src = gsrc[t4] + (size_t)row * EMB + kc * BK + c4 * 8;
                const uint32_t d = sb + (uint32_t)t4 * TILE_SM * 2 + row * (LDT*2) + c4 * 16;
                cp_async16(d, src);
            }
        }
        cp_commit();
    };

    float c[2][8][4];
#pragma unroll
    for (int mt = 0; mt < 2; mt++)
#pragma unroll
        for (int nt = 0; nt < 8; nt++)
#pragma unroll
            for (int e = 0; e < 4; e++) c[mt][nt][e] = 0.f;

    load_chunk(0, 0);
    load_chunk(1, 1);

    for (int i = 0; i < NCH; i++) {
        if (i + 2 < NCH) { load_chunk((i + 2) % STAGES, i + 2); cp_wait<2>(); }
        else if (i + 1 < NCH) cp_wait<1>();
        else cp_wait<0>();
        __syncthreads();

        const uint32_t sb  = sm0 + (uint32_t)(i % STAGES) * STAGE_SM * 2;
        const uint32_t ahb = sb;
        const uint32_t alb = sb + TILE_SM * 2;
        const uint32_t bhb = sb + 2 * TILE_SM * 2;
        const uint32_t blb = sb + 3 * TILE_SM * 2;

#pragma unroll
        for (int kk = 0; kk < 2; kk++) {
            const int k0 = kk * 16;
            // A fragments (hi & lo) for both m16 tiles
            uint32_t a_h[2][4], a_l[2][4];
            const int arow = (lane & 15);
            const int acol = k0 + ((lane >> 4) << 3);
#pragma unroll
            for (int mt = 0; mt < 2; mt++) {
                const uint32_t off = ((warp_m + mt * 16 + arow) * LDT + acol) * 2;
                ldsm_x4(a_h[mt], ahb + off);
                ldsm_x4(a_l[mt], alb + off);
            }
            const int brow = (lane & 7);
            const int bcol = k0 + (((lane >> 3) & 1) << 3);
#pragma unroll
            for (int nt = 0; nt < 8; nt++) {
                uint32_t b_h[2], b_l[2];
                const uint32_t boff = ((warp_n + nt * 8 + brow) * LDT + bcol) * 2;
                ldsm_x2(b_h, bhb + boff);
                ldsm_x2(b_l, blb + boff);
#pragma unroll
                for (int mt = 0; mt < 2; mt++) {
                    mma16816(c[mt][nt], a_h[mt], b_h);
                    mma16816(c[mt][nt], a_h[mt], b_l);
                    mma16816(c[mt][nt], a_l[mt], b_h);
                }
            }
        }
        __syncthreads();
    }

    // --- epilogue
#pragma unroll
    for (int mt = 0; mt < 2; mt++) {
#pragma unroll
        for (int nt = 0; nt < 8; nt++) {
            const int n = n0 + warp_n + nt * 8 + (lane & 3) * 2;
            const float2 bb = *(const float2*)&bias[n];
#pragma unroll
            for (int half = 0; half < 2; half++) {
                const int m = m0 + warp_m + mt * 16 + (lane >> 2) + half * 8;
                float2 r;
                r.x = c[mt][nt][half*2+0] + bb.x;
                r.y = c[mt][nt][half*2+1] + bb.y;
                if (SCATTER) {
                    const int b = m >> 11;
                    const int t = m & (SEQ - 1);
                    const int h = n >> 6;
                    const int d = n & 63;
                    *(float2*)&dst[(((size_t)(b*HEADS + h) * SEQ) + t) * HDIM + d] = r;
                } else {
                    *(float2*)&dst[(size_t)m * EMB + n] = r;
                }
            }
        }
    }
}

__global__ void __launch_bounds__(256) qkv_hgemm_kernel(
    const float* __restrict__ bq, const float* __restrict__ bk, const float* __restrict__ bv)
{
    const int z = blockIdx.z;
    const __nv_bfloat16* Wh = g_wh + (size_t)z * EMB * EMB;
    const __nv_bfloat16* Wl = g_wl + (size_t)z * EMB * EMB;
    const float* bias = (z == 0) ? bq : (z == 1) ? bk : bv;
    float* dst        = (z == 0) ? g_q : (z == 1) ? g_k : g_v;
    hgemm_body<true>(g_xh, g_xl, Wh, Wl, bias, dst);
}

__global__ void __launch_bounds__(256) proj_hgemm_kernel(
    const float* __restrict__ bo, float* __restrict__ out)
{
    hgemm_body<false>(g_ah, g_al, g_wh + (size_t)3 * EMB * EMB,
                      g_wl + (size_t)3 * EMB * EMB, bo, out);
}

// ---------------------------------------------------------------------------
// Causal flash attention (fp32 SIMT).
// ---------------------------------------------------------------------------
#define ATTN_SMEM_FLOATS (4096*3 + 64*65 + 3*64)
#define ATTN_SMEM_BYTES  (ATTN_SMEM_FLOATS * 4)

__global__ void __launch_bounds__(256) attn_kernel()
{
    extern __shared__ float smf[];
    float* Qs = smf;                 // [d][m]
    float* Ks = smf + 4096;          // [d][n]
    float* Vs = smf + 8192;          // [j][d]
    float* Ss = smf + 12288;         // [64][65]
    float* row_m = Ss + 64*65;
    float* row_l = row_m + 64;
    float* row_a = row_l + 64;

    const int tid = threadIdx.x;
    const int tx = tid & 15;
    const int ty = tid >> 4;
    const int qt = (gridDim.x - 1) - blockIdx.x;  // longest blocks first
    const int bh = blockIdx.y;

    const float* qptr = g_q + (size_t)bh * SEQ * HDIM;
    const float* kptr = g_k + (size_t)bh * SEQ * HDIM;
    const float* vptr = g_v + (size_t)bh * SEQ * HDIM;

    {
        const int m  = tid >> 4;
        const int d0 = (tid & 15) * 4;
#pragma unroll
        for (int mm = m; mm < 64; mm += 16) {
            float4 qv = *(const float4*)&qptr[(qt*64 + mm) * HDIM + d0];
            Qs[(d0+0)*64 + mm] = qv.x;
            Qs[(d0+1)*64 + mm] = qv.y;
            Qs[(d0+2)*64 + mm] = qv.z;
            Qs[(d0+3)*64 + mm] = qv.w;
        }
    }
    if (tid < 64) { row_m[tid] = -INFINITY; row_l[tid] = 0.f; }

    float acc[4][4];
#pragma unroll
    for (int a = 0; a < 4; a++)
#pragma unroll
        for (int b = 0; b < 4; b++) acc[a][b] = 0.f;

    const float LOG2E = 1.4426950408889634f;
    const float scale = 0.125f;

    for (int kt = 0; kt <= qt; kt++) {
        __syncthreads();
        {
            const int m  = tid >> 4;
            const int d0 = (tid & 15) * 4;
#pragma unroll
            for (int mm = m; mm < 64; mm += 16) {
                float4 kv = *(const float4*)&kptr[(kt*64 + mm) * HDIM + d0];
                Ks[(d0+0)*64 + mm] = kv.x;
                Ks[(d0+1)*64 + mm] = kv.y;
                Ks[(d0+2)*64 + mm] = kv.z;
                Ks[(d0+3)*64 + mm] = kv.w;
                float4 vv = *(const float4*)&vptr[(kt*64 + mm) * HDIM + d0];
                *(float4*)&Vs[mm*64 + d0] = vv;
            }
        }
        __syncthreads();

        float s[4][4];
#pragma unroll
        for (int a = 0; a < 4; a++)
#pragma unroll
            for (int b = 0; b < 4; b++) s[a][b] = 0.f;

#pragma unroll 16
        for (int d = 0; d < 64; d++) {
            float4 qv = *(const float4*)&Qs[d*64 + 4*ty];
            float4 kv = *(const float4*)&Ks[d*64 + 4*tx];
            float qa[4] = {qv.x, qv.y, qv.z, qv.w};
            float kb[4] = {kv.x, kv.y, kv.z, kv.w};
#pragma unroll
            for (int a = 0; a < 4; a++)
#pragma unroll
                for (int b = 0; b < 4; b++)
                    s[a][b] = fmaf(qa[a], kb[b], s[a][b]);
        }

        const bool diag = (kt == qt);
#pragma unroll
        for (int a = 0; a < 4; a++)
#pragma unroll
            for (int b = 0; b < 4; b++) {
                float v = s[a][b] * scale;
                if (diag && (4*tx + b > 4*ty + a)) v = -1e30f;
                Ss[(4*ty + a) * 65 + 4*tx + b] = v;
            }
        __syncthreads();

        {
            const int r  = tid >> 2;
            const int c0 = (tid & 3) * 16;
            float mx = -INFINITY;
#pragma unroll
            for (int c = 0; c < 16; c++) mx = fmaxf(mx, Ss[r*65 + c0 + c]);
            mx = fmaxf(mx, __shfl_xor_sync(0xffffffffu, mx, 1));
            mx = fmaxf(mx, __shfl_xor_sync(0xffffffffu, mx, 2));
            const float m_old = row_m[r];
            const float m_new = fmaxf(m_old, mx);
            float sum = 0.f;
#pragma unroll
            for (int c = 0; c < 16; c++) {
                float p = exp2f((Ss[r*65 + c0 + c] - m_new) * LOG2E);
                Ss[r*65 + c0 + c] = p;
                sum += p;
            }
            sum += __shfl_xor_sync(0xffffffffu, sum, 1);
            sum += __shfl_xor_sync(0xffffffffu, sum, 2);
            if ((tid & 3) == 0) {
                float alpha = exp2f((m_old - m_new) * LOG2E);
                row_a[r] = alpha;
                row_m[r] = m_new;
                row_l[r] = row_l[r] * alpha + sum;
            }
        }
        __syncthreads();

        float al[4];
#pragma unroll
        for (int a = 0; a < 4; a++) al[a] = row_a[4*ty + a];
#pragma unroll
        for (int a = 0; a < 4; a++)
#pragma unroll
            for (int b = 0; b < 4; b++) acc[a][b] *= al[a];

#pragma unroll 8
        for (int j = 0; j < 64; j++) {
            float4 vv = *(const float4*)&Vs[j*64 + 4*tx];
            float p0 = Ss[(4*ty + 0)*65 + j];
            float p1 = Ss[(4*ty + 1)*65 + j];
            float p2 = Ss[(4*ty + 2)*65 + j];
            float p3 = Ss[(4*ty + 3)*65 + j];
            acc[0][0] = fmaf(p0, vv.x, acc[0][0]); acc[0][1] = fmaf(p0, vv.y, acc[0][1]);
            acc[0][2] = fmaf(p0, vv.z, acc[0][2]); acc[0][3] = fmaf(p0, vv.w, acc[0][3]);
            acc[1][0] = fmaf(p1, vv.x, acc[1][0]); acc[1][1] = fmaf(p1, vv.y, acc[1][1]);
            acc[1][2] = fmaf(p1, vv.z, acc[1][2]); acc[1][3] = fmaf(p1, vv.w, acc[1][3]);
            acc[2][0] = fmaf(p2, vv.x, acc[2][0]); acc[2][1] = fmaf(p2, vv.y, acc[2][1]);
            acc[2][2] = fmaf(p2, vv.z, acc[2][2]); acc[2][3] = fmaf(p2, vv.w, acc[2][3]);
            acc[3][0] = fmaf(p3, vv.x, acc[3][0]); acc[3][1] = fmaf(p3, vv.y, acc[3][1]);
            acc[3][2] = fmaf(p3, vv.z, acc[3][2]); acc[3][3] = fmaf(p3, vv.w, acc[3][3]);
        }
    }

    const int b = bh >> 4;
    const int h = bh & 15;
#pragma unroll
    for (int a = 0; a < 4; a++) {
        const float inv = 1.0f / row_l[4*ty + a];
        const int t = qt*64 + 4*ty + a;
        float4 r;
        r.x = acc[a][0] * inv; r.y = acc[a][1] * inv;
        r.z = acc[a][2] * inv; r.w = acc[a][3] * inv;
        *(float4*)&g_attn[((size_t)(b*SEQ + t)) * EMB + h*HDIM + 4*tx] = r;
    }
}

// ---------------------------------------------------------------------------
extern "C" void kernel_launch(void* const* d_in, const int* in_sizes, int n_in,
                              void* d_out, int out_size)
{
    const float* x   = (const float*)d_in[0];
    const float* W_q = (const float*)d_in[1];
    const float* b_q = (const float*)d_in[2];
    const float* W_k = (const float*)d_in[3];
    const float* b_k = (const float*)d_in[4];
    const float* W_v = (const float*)d_in[5];
    const float* b_v = (const float*)d_in[6];
    const float* W_o = (const float*)d_in[7];
    const float* b_o = (const float*)d_in[8];
    float* out = (float*)d_out;

    static bool attr_set = false;
    if (!attr_set) {
        cudaFuncSetAttribute(attn_kernel,
                             cudaFuncAttributeMaxDynamicSharedMemorySize, ATTN_SMEM_BYTES);
        cudaFuncSetAttribute(qkv_hgemm_kernel,
                             cudaFuncAttributeMaxDynamicSharedMemorySize, GSMEM_BYTES);
        cudaFuncSetAttribute(proj_hgemm_kernel,
                             cudaFuncAttributeMaxDynamicSharedMemorySize, GSMEM_BYTES);
        attr_set = true;
    }

    // resolve device-global scratch addresses
    __nv_bfloat16 *xh, *xl, *wh, *wl, *ah, *al;
    float *attn_f;
    cudaGetSymbolAddress((void**)&xh, g_xh);
    cudaGetSymbolAddress((void**)&xl, g_xl);
    cudaGetSymbolAddress((void**)&wh, g_wh);
    cudaGetSymbolAddress((void**)&wl, g_wl);
    cudaGetSymbolAddress((void**)&ah, g_ah);
    cudaGetSymbolAddress((void**)&al, g_al);
    cudaGetSymbolAddress((void**)&attn_f, g_attn);

    // 1) split conversions
    {
        int n4 = MROWS * EMB / 4;
        convert_split_kernel<<<(n4 + 255) / 256, 256>>>(x, xh, xl, n4);
        int w4 = EMB * EMB / 4;
        convert_split_kernel<<<(w4 + 255) / 256, 256>>>(W_q, wh + 0*EMB*EMB, wl + 0*EMB*EMB, w4);
        convert_split_kernel<<<(w4 + 255) / 256, 256>>>(W_k, wh + 1*EMB*EMB, wl + 1*EMB*EMB, w4);
        convert_split_kernel<<<(w4 + 255) / 256, 256>>>(W_v, wh + 2*EMB*EMB, wl + 2*EMB*EMB, w4);
        convert_split_kernel<<<(w4 + 255) / 256, 256>>>(W_o, wh + 3*EMB*EMB, wl + 3*EMB*EMB, w4);
    }

    // 2) QKV projections on HMMA tensor cores
    dim3 gqkv(MROWS/128, EMB/128, 3);
    qkv_hgemm_kernel<<<gqkv, 256, GSMEM_BYTES>>>(b_q, b_k, b_v);

    // 3) attention
    dim3 gattn(SEQ/64, BATCH*HEADS);
    attn_kernel<<<gattn, 256, ATTN_SMEM_BYTES>>>();

    // 4) convert attention output, output projection
    {
        int n4 = MROWS * EMB / 4;
        convert_split_kernel<<<(n4 + 255) / 256, 256>>>(attn_f, ah, al, n4);
    }
    dim3 gproj(MROWS/128, EMB/128);
    proj_hgemm_kernel<<<gproj, 256, GSMEM_BYTES>>>(b_o, out);
}

// round 4
// speedup vs baseline: 2.8355x; 2.1870x over previous
#include <cuda_runtime.h>
#include <cuda_bf16.h>
#include <cuda_fp16.h>
#include <cstdint>
#include <cmath>

// Problem constants
#define BATCH 2
#define SEQ   2048
#define EMB   1024
#define HEADS 16
#define HDIM  64
#define MROWS (BATCH*SEQ)   // 4096

// Scratch (device globals; no allocation allowed)
__device__ __half g_q16[BATCH*HEADS*SEQ*HDIM];   // (B,H,T,D), pre-scaled by 0.125
__device__ __half g_k16[BATCH*HEADS*SEQ*HDIM];   // (B,H,T,D)
__device__ __half g_v16[BATCH*HEADS*SEQ*HDIM];   // (B,H,D,T)  transposed!
__device__ __nv_bfloat16 g_xh[MROWS*EMB];
__device__ __nv_bfloat16 g_xl[MROWS*EMB];
__device__ __nv_bfloat16 g_wh[4*EMB*EMB];
__device__ __nv_bfloat16 g_wl[4*EMB*EMB];
__device__ __nv_bfloat16 g_ah[MROWS*EMB];        // attention out hi (B,T,C)
__device__ __nv_bfloat16 g_al[MROWS*EMB];        // attention out lo

// ---------------------------------------------------------------------------
// PTX helpers (family-level: sm_80+ instructions only)
// ---------------------------------------------------------------------------
__device__ __forceinline__ uint32_t smem_u32(const void* p) {
    uint32_t a;
    asm("{ .reg .u64 t; cvta.to.shared.u64 t, %1; cvt.u32.u64 %0, t; }" : "=r"(a) : "l"(p));
    return a;
}
__device__ __forceinline__ void cp_async16(uint32_t dst, const void* src) {
    asm volatile("cp.async.cg.shared.global [%0], [%1], 16;" :: "r"(dst), "l"(src));
}
__device__ __forceinline__ void cp_commit() {
    asm volatile("cp.async.commit_group;" ::: "memory");
}
template<int N>
__device__ __forceinline__ void cp_wait() {
    asm volatile("cp.async.wait_group %0;" :: "n"(N) : "memory");
}
__device__ __forceinline__ void ldsm_x4(uint32_t* r, uint32_t addr) {
    asm volatile("ldmatrix.sync.aligned.m8n8.x4.shared.b16 {%0,%1,%2,%3}, [%4];"
                 : "=r"(r[0]), "=r"(r[1]), "=r"(r[2]), "=r"(r[3]) : "r"(addr));
}
__device__ __forceinline__ void ldsm_x2(uint32_t* r, uint32_t addr) {
    asm volatile("ldmatrix.sync.aligned.m8n8.x2.shared.b16 {%0,%1}, [%2];"
                 : "=r"(r[0]), "=r"(r[1]) : "r"(addr));
}
__device__ __forceinline__ void mma16816(float* c, const uint32_t* a, const uint32_t* b) {
    asm volatile(
        "mma.sync.aligned.m16n8k16.row.col.f32.bf16.bf16.f32 "
        "{%0,%1,%2,%3}, {%4,%5,%6,%7}, {%8,%9}, {%0,%1,%2,%3};"
        : "+f"(c[0]), "+f"(c[1]), "+f"(c[2]), "+f"(c[3])
        : "r"(a[0]), "r"(a[1]), "r"(a[2]), "r"(a[3]), "r"(b[0]), "r"(b[1]));
}
__device__ __forceinline__ void mma16816h(float* c, const uint32_t* a, const uint32_t* b) {
    asm volatile(
        "mma.sync.aligned.m16n8k16.row.col.f32.f16.f16.f32 "
        "{%0,%1,%2,%3}, {%4,%5,%6,%7}, {%8,%9}, {%0,%1,%2,%3};"
        : "+f"(c[0]), "+f"(c[1]), "+f"(c[2]), "+f"(c[3])
        : "r"(a[0]), "r"(a[1]), "r"(a[2]), "r"(a[3]), "r"(b[0]), "r"(b[1]));
}
// pack two fp32 -> f16x2 (lo in low half)
__device__ __forceinline__ uint32_t pack_h2(float lo, float hi) {
    uint32_t r;
    asm("cvt.rn.f16x2.f32 %0, %1, %2;" : "=r"(r) : "f"(hi), "f"(lo));
    return r;
}

// ---------------------------------------------------------------------------
// fp32 -> (bf16 hi, bf16 lo) split
// ---------------------------------------------------------------------------
__global__ void __launch_bounds__(256) convert_split_kernel(
    const float* __restrict__ src,
    __nv_bfloat16* __restrict__ hi, __nv_bfloat16* __restrict__ lo, int n4)
{
    int i = blockIdx.x * blockDim.x + threadIdx.x;
    if (i >= n4) return;
    float4 v = ((const float4*)src)[i];
    __nv_bfloat16 h0 = __float2bfloat16(v.x);
    __nv_bfloat16 h1 = __float2bfloat16(v.y);
    __nv_bfloat16 h2 = __float2bfloat16(v.z);
    __nv_bfloat16 h3 = __float2bfloat16(v.w);
    __nv_bfloat16 l0 = __float2bfloat16(v.x - __bfloat162float(h0));
    __nv_bfloat16 l1 = __float2bfloat16(v.y - __bfloat162float(h1));
    __nv_bfloat16 l2 = __float2bfloat16(v.z - __bfloat162float(h2));
    __nv_bfloat16 l3 = __float2bfloat16(v.w - __bfloat162float(h3));
    __nv_bfloat162 hv0; hv0.x = h0; hv0.y = h1;
    __nv_bfloat162 hv1; hv1.x = h2; hv1.y = h3;
    __nv_bfloat162 lv0; lv0.x = l0; lv0.y = l1;
    __nv_bfloat162 lv1; lv1.x = l2; lv1.y = l3;
    ((__nv_bfloat162*)hi)[2*i]   = hv0;
    ((__nv_bfloat162*)hi)[2*i+1] = hv1;
    ((__nv_bfloat162*)lo)[2*i]   = lv0;
    ((__nv_bfloat162*)lo)[2*i+1] = lv1;
}

// ---------------------------------------------------------------------------
// HMMA GEMM: out[m][n] = sum_k A[m][k]*W[n][k] + bias[n], 3x-bf16 split.
// CTA: 128x128 tile, 256 threads, 8 warps (4x2), warp tile 32x64.
// MODE: 0 = fp32 row-major out; 1 = Q fp16 scaled (B,H,T,D);
//       2 = K fp16 (B,H,T,D);   3 = V fp16 transposed (B,H,D,T)
// ---------------------------------------------------------------------------
#define BK 32
#define LDT 40
#define TILE_SM (128*LDT)
#define STAGE_SM (4*TILE_SM)
#define STAGES 3
#define NCH (EMB/BK)
#define GSMEM_BYTES (STAGES*STAGE_SM*2)

template<int MODE>
__device__ __forceinline__ void hgemm_body(
    const __nv_bfloat16* __restrict__ Ah, const __nv_bfloat16* __restrict__ Al,
    const __nv_bfloat16* __restrict__ Bh, const __nv_bfloat16* __restrict__ Bl,
    const float* __restrict__ bias, void* __restrict__ dst)
{
    extern __shared__ __nv_bfloat16 smb[];
    const uint32_t sm0 = smem_u32(smb);

    const int tid  = threadIdx.x;
    const int wid  = tid >> 5;
    const int lane = tid & 31;
    const int m0 = blockIdx.x * 128;
    const int n0 = blockIdx.y * 128;
    const int warp_m = (wid >> 1) * 32;
    const int warp_n = (wid & 1) * 64;

    const __nv_bfloat16* gsrc[4];
    gsrc[0] = Ah + (size_t)m0 * EMB;
    gsrc[1] = Al + (size_t)m0 * EMB;
    gsrc[2] = Bh + (size_t)n0 * EMB;
    gsrc[3] = Bl + (size_t)n0 * EMB;

    auto load_chunk = [&](int stage, int kc) {
        const uint32_t sb = sm0 + (uint32_t)stage * STAGE_SM * 2;
#pragma unroll
        for (int t4 = 0; t4 < 4; t4++) {
#pragma unroll
            for (int e = 0; e < 2; e++) {
                const int idx = tid * 2 + e;
                const int row = idx >> 2;
                const int c4  = idx & 3;
                const void* src = gsrc[t4] + (size_t)row * EMB + kc * BK + c4 * 8;
                const uint32_t d = sb + (uint32_t)t4 * TILE_SM * 2 + row * (LDT*2) + c4 * 16;
                cp_async16(d, src);
            }
        }
        cp_commit();
    };

    float c[2][8][4];
#pragma unroll
    for (int mt = 0; mt < 2; mt++)
#pragma unroll
        for (int nt = 0; nt < 8; nt++)
#pragma unroll
            for (int e = 0; e < 4; e++) c[mt][nt][e] = 0.f;

    load_chunk(0, 0);
    load_chunk(1, 1);

    for (int i = 0; i < NCH; i++) {
        if (i + 2 < NCH) { load_chunk((i + 2) % STAGES, i + 2); cp_wait<2>(); }
        else if (i + 1 < NCH) cp_wait<1>();
        else cp_wait<0>();
        __syncthreads();

        const uint32_t sb  = sm0 + (uint32_t)(i % STAGES) * STAGE_SM * 2;
        const uint32_t ahb = sb;
        const uint32_t alb = sb + TILE_SM * 2;
        const uint32_t bhb = sb + 2 * TILE_SM * 2;
        const uint32_t blb = sb + 3 * TILE_SM * 2;

#pragma unroll
        for (int kk = 0; kk < 2; kk++) {
            const int k0 = kk * 16;
            uint32_t a_h[2][4], a_l[2][4];
            const int arow = (lane & 15);
            const int acol = k0 + ((lane >> 4) << 3);
#pragma unroll
            for (int mt = 0; mt < 2; mt++) {
                const uint32_t off = ((warp_m + mt * 16 + arow) * LDT + acol) * 2;
                ldsm_x4(a_h[mt], ahb + off);
                ldsm_x4(a_l[mt], alb + off);
            }
            const int brow = (lane & 7);
            const int bcol = k0 + (((lane >> 3) & 1) << 3);
#pragma unroll
            for (int nt = 0; nt < 8; nt++) {
                uint32_t b_h[2], b_l[2];
                const uint32_t boff = ((warp_n + nt * 8 + brow) * LDT + bcol) * 2;
                ldsm_x2(b_h, bhb + boff);
                ldsm_x2(b_l, blb + boff);
#pragma unroll
                for (int mt = 0; mt < 2; mt++) {
                    mma16816(c[mt][nt], a_h[mt], b_h);
                    mma16816(c[mt][nt], a_h[mt], b_l);
                    mma16816(c[mt][nt], a_l[mt], b_h);
                }
            }
        }
        __syncthreads();
    }

    // --- epilogue
#pragma unroll
    for (int mt = 0; mt < 2; mt++) {
#pragma unroll
        for (int nt = 0; nt < 8; nt++) {
            const int n = n0 + warp_n + nt * 8 + (lane & 3) * 2;
            const float2 bb = *(const float2*)&bias[n];
#pragma unroll
            for (int half = 0; half < 2; half++) {
                const int m = m0 + warp_m + mt * 16 + (lane >> 2) + half * 8;
                float rx = c[mt][nt][half*2+0] + bb.x;
                float ry = c[mt][nt][half*2+1] + bb.y;
                if (MODE == 0) {
                    float2 r; r.x = rx; r.y = ry;
                    *(float2*)((float*)dst + (size_t)m * EMB + n) = r;
                } else {
                    const int bh = ((m >> 11) << 4) + (n >> 6);  // b*16 + h
                    const int t  = m & (SEQ - 1);
                    const int d  = n & 63;
                    if (MODE == 1) {
                        __half2 hv;
                        hv.x = __float2half_rn(rx * 0.125f);
                        hv.y = __float2half_rn(ry * 0.125f);
                        *(__half2*)((__half*)dst + ((size_t)bh * SEQ + t) * HDIM + d) = hv;
                    } else if (MODE == 2) {
                        __half2 hv;
                        hv.x = __float2half_rn(rx);
                        hv.y = __float2half_rn(ry);
                        *(__half2*)((__half*)dst + ((size_t)bh * SEQ + t) * HDIM + d) = hv;
                    } else {
                        __half* p = (__half*)dst + ((size_t)bh * HDIM + d) * SEQ + t;
                        p[0]   = __float2half_rn(rx);
                        p[SEQ] = __float2half_rn(ry);
                    }
                }
            }
        }
    }
}

__global__ void __launch_bounds__(256) qkv_hgemm_kernel(
    const float* __restrict__ bq, const float* __restrict__ bk, const float* __restrict__ bv)
{
    const int z = blockIdx.z;
    if (z == 0)
        hgemm_body<1>(g_xh, g_xl, g_wh, g_wl, bq, g_q16);
    else if (z == 1)
        hgemm_body<2>(g_xh, g_xl, g_wh + (size_t)EMB*EMB, g_wl + (size_t)EMB*EMB, bk, g_k16);
    else
        hgemm_body<3>(g_xh, g_xl, g_wh + (size_t)2*EMB*EMB, g_wl + (size_t)2*EMB*EMB, bv, g_v16);
}

__global__ void __launch_bounds__(256) proj_hgemm_kernel(
    const float* __restrict__ bo, float* __restrict__ out)
{
    hgemm_body<0>(g_ah, g_al, g_wh + (size_t)3*EMB*EMB, g_wl + (size_t)3*EMB*EMB, bo, out);
}

// ---------------------------------------------------------------------------
// HMMA causal flash attention, all-fp16 operands, fp32 accum.
// CTA: 128 queries x one (b,h). 8 warps, each owns 16 query rows.
// KV tiles of 64, double-buffered cp.async. Q scaled by 0.125 already.
// ---------------------------------------------------------------------------
#define ALD 72                       // fp16 per smem row (144 B)
#define QS_BYTES (128*ALD*2)         // 18432
#define KV_STAGE_BYTES (2*64*ALD*2)  // K + V per stage = 18432
#define ATTN_SMEM (QS_BYTES + 2*KV_STAGE_BYTES)   // 55296

__global__ void __launch_bounds__(256) attn_hmma_kernel()
{
    extern __shared__ char smc[];
    const uint32_t sm0 = smem_u32(smc);

    const int tid  = threadIdx.x;
    const int wid  = tid >> 5;
    const int lane = tid & 31;
    const int qt = (gridDim.x - 1) - blockIdx.x;   // longest first
    const int bh = blockIdx.y;

    const __half* qg = g_q16 + (size_t)bh * SEQ * HDIM;   // [t][d]
    const __half* kg = g_k16 + (size_t)bh * SEQ * HDIM;   // [t][d]
    const __half* vg = g_v16 + (size_t)bh * HDIM * SEQ;   // [d][t]

    // ---- issue Q tile load (group 0): 128 rows x 128B
#pragma unroll
    for (int e = 0; e < 4; e++) {
        const int idx = tid * 4 + e;        // 0..1023
        const int row = idx >> 3;
        const int ch  = idx & 7;
        cp_async16(sm0 + row * (ALD*2) + ch * 16,
                   qg + ((size_t)qt * 128 + row) * HDIM + ch * 8);
    }
    cp_commit();

    auto load_kv = [&](int stage, int kt) {
        const uint32_t sb = sm0 + QS_BYTES + (uint32_t)stage * KV_STAGE_BYTES;
#pragma unroll
        for (int e = 0; e < 2; e++) {
            const int idx = tid * 2 + e;    // 0..511
            const int row = idx >> 3;
            const int ch  = idx & 7;
            cp_async16(sb + row * (ALD*2) + ch * 16,
                       kg + ((size_t)kt * 64 + row) * HDIM + ch * 8);
            cp_async16(sb + 64*(ALD*2) + row * (ALD*2) + ch * 16,
                       vg + (size_t)row * SEQ + kt * 64 + ch * 8);
        }
        cp_commit();
    };

    const int nkv = 2 * qt + 2;
    load_kv(0, 0);

    cp_wait<1>();      // Q tile ready
    __syncthreads();

    // ---- Q fragments (per warp, rows wid*16..+15), 4 k-steps
    uint32_t aq[4][4];
    {
        const int arow = lane & 15;
        const int acol = (lane >> 4) << 3;
#pragma unroll
        for (int kk = 0; kk < 4; kk++)
            ldsm_x4(aq[kk], sm0 + ((wid*16 + arow) * ALD + kk*16 + acol) * 2);
    }

    float o[8][4];
#pragma unroll
    for (int nt = 0; nt < 8; nt++)
#pragma unroll
        for (int e = 0; e < 4; e++) o[nt][e] = 0.f;
    float m0r = -INFINITY, m1r = -INFINITY, l0r = 0.f, l1r = 0.f;

    const float LOG2E = 1.4426950408889634f;
    const int rbase = qt*128 + wid*16 + (lane >> 2);

    for (int kt = 0; kt < nkv; kt++) {
        if (kt + 1 < nkv) { load_kv((kt + 1) & 1, kt + 1); cp_wait<1>(); }
        else cp_wait<0>();
        __syncthreads();

        const uint32_t kb = sm0 + QS_BYTES + (uint32_t)(kt & 1) * KV_STAGE_BYTES;
        const uint32_t vb = kb + 64*(ALD*2);

        // ---- S = Q K^T
        float s[8][4];
#pragma unroll
        for (int nt = 0; nt < 8; nt++)
#pragma unroll
            for (int e = 0; e < 4; e++) s[nt][e] = 0.f;

        const int lrow = lane & 15;
        const int lcol = (lane >> 4) << 3;
#pragma unroll
        for (int kk = 0; kk < 4; kk++) {
#pragma unroll
            for (int nt2 = 0; nt2 < 4; nt2++) {
                uint32_t br[4];
                ldsm_x4(br, kb + ((nt2*16 + lrow) * ALD + kk*16 + lcol) * 2);
                uint32_t b0[2] = {br[0], br[2]};
                uint32_t b1[2] = {br[1], br[3]};
                mma16816h(s[2*nt2],   aq[kk], b0);
                mma16816h(s[2*nt2+1], aq[kk], b1);
            }
        }

        // ---- causal mask (diagonal region only)
        if (kt >= 2*qt) {
#pragma unroll
            for (int nt = 0; nt < 8; nt++) {
                const int col = kt*64 + nt*8 + (lane & 3)*2;
#pragma unroll
                for (int e = 0; e < 4; e++) {
                    const int cc = col + (e & 1);
                    const int rr = rbase + (e >> 1)*8;
                    if (cc > rr) s[nt][e] = -1e30f;
                }
            }
        }

        // ---- online softmax (rows r0 = lane>>2, r1 = r0+8; quad-lane reduce)
        float mx0 = -INFINITY, mx1 = -INFINITY;
#pragma unroll
        for (int nt = 0; nt < 8; nt++) {
            mx0 = fmaxf(mx0, fmaxf(s[nt][0], s[nt][1]));
            mx1 = fmaxf(mx1, fmaxf(s[nt][2], s[nt][3]));
        }
        mx0 = fmaxf(mx0, __shfl_xor_sync(0xffffffffu, mx0, 1));
        mx0 = fmaxf(mx0, __shfl_xor_sync(0xffffffffu, mx0, 2));
        mx1 = fmaxf(mx1, __shfl_xor_sync(0xffffffffu, mx1, 1));
        mx1 = fmaxf(mx1, __shfl_xor_sync(0xffffffffu, mx1, 2));
        const float mn0 = fmaxf(m0r, mx0);
        const float mn1 = fmaxf(m1r, mx1);
        const float a0 = exp2f((m0r - mn0) * LOG2E);
        const float a1 = exp2f((m1r - mn1) * LOG2E);
        m0r = mn0; m1r = mn1;

        float rs0 = 0.f, rs1 = 0.f;
#pragma unroll
        for (int nt = 0; nt < 8; nt++) {
            float p0 = exp2f((s[nt][0] - mn0) * LOG2E);
            float p1 = exp2f((s[nt][1] - mn0) * LOG2E);
            float p2 = exp2f((s[nt][2] - mn1) * LOG2E);
            float p3 = exp2f((s[nt][3] - mn1) * LOG2E);
            s[nt][0] = p0; s[nt][1] = p1; s[nt][2] = p2; s[nt][3] = p3;
            rs0 += p0 + p1; rs1 += p2 + p3;
        }
        rs0 += __shfl_xor_sync(0xffffffffu, rs0, 1);
        rs0 += __shfl_xor_sync(0xffffffffu, rs0, 2);
        rs1 += __shfl_xor_sync(0xffffffffu, rs1, 1);
        rs1 += __shfl_xor_sync(0xffffffffu, rs1, 2);
        l0r = l0r * a0 + rs0;
        l1r = l1r * a1 + rs1;

#pragma unroll
        for (int nt = 0; nt < 8; nt++) {
            o[nt][0] *= a0; o[nt][1] *= a0;
            o[nt][2] *= a1; o[nt][3] *= a1;
        }

        // ---- P fragments (C-frag -> A-frag identity)
        uint32_t pf[4][4];
#pragma unroll
        for (int kk = 0; kk < 4; kk++) {
            pf[kk][0] = pack_h2(s[2*kk][0],   s[2*kk][1]);
            pf[kk][1] = pack_h2(s[2*kk][2],   s[2*kk][3]);
            pf[kk][2] = pack_h2(s[2*kk+1][0], s[2*kk+1][1]);
            pf[kk][3] = pack_h2(s[2*kk+1][2], s[2*kk+1][3]);
        }

        // ---- O += P V   (V^T in smem: [d][kv])
#pragma unroll
        for (int kk = 0; kk < 4; kk++) {
#pragma unroll
            for (int nt2 = 0; nt2 < 4; nt2++) {
                uint32_t br[4];
                ldsm_x4(br, vb + ((nt2*16 + lrow) * ALD + kk*16 + lcol) * 2);
                uint32_t b0[2] = {br[0], br[2]};
                uint32_t b1[2] = {br[1], br[3]};
                mma16816h(o[2*nt2],   pf[kk], b0);
                mma16816h(o[2*nt2+1], pf[kk], b1);
            }
        }
        __syncthreads();
    }

    // ---- finalize: write bf16 hi/lo into (B,T,C)
    const float inv0 = 1.f / l0r;
    const float inv1 = 1.f / l1r;
    const int b = bh >> 4;
    const int h = bh & 15;
    const int t0 = qt*128 + wid*16 + (lane >> 2);
#pragma unroll
    for (int nt = 0; nt < 8; nt++) {
        const int d = nt*8 + (lane & 3)*2;
#pragma unroll
        for (int half = 0; half < 2; half++) {
            const int t = t0 + half*8;
            const float inv = half ? inv1 : inv0;
            const float vx = o[nt][half*2+0] * inv;
            const float vy = o[nt][half*2+1] * inv;
            __nv_bfloat16 hx = __float2bfloat16(vx);
            __nv_bfloat16 hy = __float2bfloat16(vy);
            __nv_bfloat162 hv; hv.x = hx; hv.y = hy;
            __nv_bfloat162 lv;
            lv.x = __float2bfloat16(vx - __bfloat162float(hx));
            lv.y = __float2bfloat16(vy - __bfloat162float(hy));
            const size_t off = ((size_t)(b*SEQ + t)) * EMB + h*HDIM + d;
            *(__nv_bfloat162*)&g_ah[off] = hv;
            *(__nv_bfloat162*)&g_al[off] = lv;
        }
    }
}

// ---------------------------------------------------------------------------
extern "C" void kernel_launch(void* const* d_in, const int* in_sizes, int n_in,
                              void* d_out, int out_size)
{
    const float* x   = (const float*)d_in[0];
    const float* W_q = (const float*)d_in[1];
    const float* b_q = (const float*)d_in[2];
    const float* W_k = (const float*)d_in[3];
    const float* b_k = (const float*)d_in[4];
    const float* W_v = (const float*)d_in[5];
    const float* b_v = (const float*)d_in[6];
    const float* W_o = (const float*)d_in[7];
    const float* b_o = (const float*)d_in[8];
    float* out = (float*)d_out;

    static bool attr_set = false;
    if (!attr_set) {
        cudaFuncSetAttribute(attn_hmma_kernel,
                             cudaFuncAttributeMaxDynamicSharedMemorySize, ATTN_SMEM);
        cudaFuncSetAttribute(qkv_hgemm_kernel,
                             cudaFuncAttributeMaxDynamicSharedMemorySize, GSMEM_BYTES);
        cudaFuncSetAttribute(proj_hgemm_kernel,
                             cudaFuncAttributeMaxDynamicSharedMemorySize, GSMEM_BYTES);
        attr_set = true;
    }

    __nv_bfloat16 *xh, *xl, *wh, *wl;
    cudaGetSymbolAddress((void**)&xh, g_xh);
    cudaGetSymbolAddress((void**)&xl, g_xl);
    cudaGetSymbolAddress((void**)&wh, g_wh);
    cudaGetSymbolAddress((void**)&wl, g_wl);

    // 1) split conversions (x and 4 weights)
    {
        int n4 = MROWS * EMB / 4;
        convert_split_kernel<<<(n4 + 255) / 256, 256>>>(x, xh, xl, n4);
        int w4 = EMB * EMB / 4;
        convert_split_kernel<<<(w4 + 255) / 256, 256>>>(W_q, wh + 0*(size_t)EMB*EMB, wl + 0*(size_t)EMB*EMB, w4);
        convert_split_kernel<<<(w4 + 255) / 256, 256>>>(W_k, wh + 1*(size_t)EMB*EMB, wl + 1*(size_t)EMB*EMB, w4);
        convert_split_kernel<<<(w4 + 255) / 256, 256>>>(W_v, wh + 2*(size_t)EMB*EMB, wl + 2*(size_t)EMB*EMB, w4);
        convert_split_kernel<<<(w4 + 255) / 256, 256>>>(W_o, wh + 3*(size_t)EMB*EMB, wl + 3*(size_t)EMB*EMB, w4);
    }

    // 2) QKV projections (writes fp16 q/k and transposed v)
    dim3 gqkv(MROWS/128, EMB/128, 3);
    qkv_hgemm_kernel<<<gqkv, 256, GSMEM_BYTES>>>(b_q, b_k, b_v);

    // 3) HMMA flash attention (writes bf16 hi/lo attention output)
    dim3 gattn(SEQ/128, BATCH*HEADS);
    attn_hmma_kernel<<<gattn, 256, ATTN_SMEM>>>();

    // 4) output projection
    dim3 gproj(MROWS/128, EMB/128);
    proj_hgemm_kernel<<<gproj, 256, GSMEM_BYTES>>>(b_o, out);
}

// round 5
// speedup vs baseline: 3.1815x; 1.1220x over previous
#include <cuda_runtime.h>
#include <cuda_bf16.h>
#include <cuda_fp16.h>
#include <cstdint>
#include <cmath>

// Problem constants
#define BATCH 2
#define SEQ   2048
#define EMB   1024
#define HEADS 16
#define HDIM  64
#define MROWS (BATCH*SEQ)   // 4096

// Scratch (device globals; no allocation allowed)
__device__ __half g_q16[BATCH*HEADS*SEQ*HDIM];   // (B,H,T,D), pre-scaled by 0.125
__device__ __half g_k16[BATCH*HEADS*SEQ*HDIM];   // (B,H,T,D)
__device__ __half g_v16[BATCH*HEADS*SEQ*HDIM];   // (B,H,D,T)  transposed!
__device__ __nv_bfloat16 g_xh[MROWS*EMB];
__device__ __nv_bfloat16 g_xl[MROWS*EMB];
__device__ __nv_bfloat16 g_wh[4*EMB*EMB];
__device__ __nv_bfloat16 g_wl[4*EMB*EMB];
__device__ __nv_bfloat16 g_ah[MROWS*EMB];        // attention out hi (B,T,C)
__device__ __nv_bfloat16 g_al[MROWS*EMB];        // attention out lo

// ---------------------------------------------------------------------------
// PTX helpers (family-level: sm_80+ instructions only)
// ---------------------------------------------------------------------------
__device__ __forceinline__ uint32_t smem_u32(const void* p) {
    uint32_t a;
    asm("{ .reg .u64 t; cvta.to.shared.u64 t, %1; cvt.u32.u64 %0, t; }" : "=r"(a) : "l"(p));
    return a;
}
__device__ __forceinline__ void cp_async16(uint32_t dst, const void* src) {
    asm volatile("cp.async.cg.shared.global [%0], [%1], 16;" :: "r"(dst), "l"(src));
}
__device__ __forceinline__ void cp_commit() {
    asm volatile("cp.async.commit_group;" ::: "memory");
}
template<int N>
__device__ __forceinline__ void cp_wait() {
    asm volatile("cp.async.wait_group %0;" :: "n"(N) : "memory");
}
__device__ __forceinline__ void ldsm_x4(uint32_t* r, uint32_t addr) {
    asm volatile("ldmatrix.sync.aligned.m8n8.x4.shared.b16 {%0,%1,%2,%3}, [%4];"
                 : "=r"(r[0]), "=r"(r[1]), "=r"(r[2]), "=r"(r[3]) : "r"(addr));
}
__device__ __forceinline__ void mma16816(float* c, const uint32_t* a, const uint32_t* b) {
    asm volatile(
        "mma.sync.aligned.m16n8k16.row.col.f32.bf16.bf16.f32 "
        "{%0,%1,%2,%3}, {%4,%5,%6,%7}, {%8,%9}, {%0,%1,%2,%3};"
        : "+f"(c[0]), "+f"(c[1]), "+f"(c[2]), "+f"(c[3])
        : "r"(a[0]), "r"(a[1]), "r"(a[2]), "r"(a[3]), "r"(b[0]), "r"(b[1]));
}
__device__ __forceinline__ void mma16816h(float* c, const uint32_t* a, const uint32_t* b) {
    asm volatile(
        "mma.sync.aligned.m16n8k16.row.col.f32.f16.f16.f32 "
        "{%0,%1,%2,%3}, {%4,%5,%6,%7}, {%8,%9}, {%0,%1,%2,%3};"
        : "+f"(c[0]), "+f"(c[1]), "+f"(c[2]), "+f"(c[3])
        : "r"(a[0]), "r"(a[1]), "r"(a[2]), "r"(a[3]), "r"(b[0]), "r"(b[1]));
}
// pack two fp32 -> f16x2 (lo in low half)
__device__ __forceinline__ uint32_t pack_h2(float lo, float hi) {
    uint32_t r;
    asm("cvt.rn.f16x2.f32 %0, %1, %2;" : "=r"(r) : "f"(hi), "f"(lo));
    return r;
}

// Swizzle for 64B logical rows packed 2-per-128B-line (GEMM tiles, BK=32 bf16).
// row 0..127, ch 0..3 (16B chunks). Conflict-free for ldmatrix row sets.
__device__ __forceinline__ uint32_t sw64(int row, int ch) {
    const int line = row >> 1;
    const int pos  = ((row & 1) * 4 + ch) ^ (line & 7);
    return (uint32_t)(line * 128 + pos * 16);
}
// Swizzle for exact 128B rows (attention tiles, 64 fp16). row any, ch 0..7.
__device__ __forceinline__ uint32_t sw128(int row, int ch) {
    return (uint32_t)(row * 128 + ((ch ^ (row & 7)) * 16));
}

// ---------------------------------------------------------------------------
// fp32 -> (bf16 hi, bf16 lo) split
// ---------------------------------------------------------------------------
__global__ void __launch_bounds__(256) convert_split_kernel(
    const float* __restrict__ src,
    __nv_bfloat16* __restrict__ hi, __nv_bfloat16* __restrict__ lo, int n4)
{
    int i = blockIdx.x * blockDim.x + threadIdx.x;
    if (i >= n4) return;
    float4 v = ((const float4*)src)[i];
    __nv_bfloat16 h0 = __float2bfloat16(v.x);
    __nv_bfloat16 h1 = __float2bfloat16(v.y);
    __nv_bfloat16 h2 = __float2bfloat16(v.z);
    __nv_bfloat16 h3 = __float2bfloat16(v.w);
    __nv_bfloat16 l0 = __float2bfloat16(v.x - __bfloat162float(h0));
    __nv_bfloat16 l1 = __float2bfloat16(v.y - __bfloat162float(h1));
    __nv_bfloat16 l2 = __float2bfloat16(v.z - __bfloat162float(h2));
    __nv_bfloat16 l3 = __float2bfloat16(v.w - __bfloat162float(h3));
    __nv_bfloat162 hv0; hv0.x = h0; hv0.y = h1;
    __nv_bfloat162 hv1; hv1.x = h2; hv1.y = h3;
    __nv_bfloat162 lv0; lv0.x = l0; lv0.y = l1;
    __nv_bfloat162 lv1; lv1.x = l2; lv1.y = l3;
    ((__nv_bfloat162*)hi)[2*i]   = hv0;
    ((__nv_bfloat162*)hi)[2*i+1] = hv1;
    ((__nv_bfloat162*)lo)[2*i]   = lv0;
    ((__nv_bfloat162*)lo)[2*i+1] = lv1;
}

// ---------------------------------------------------------------------------
// HMMA GEMM: out[m][n] = sum_k A[m][k]*W[n][k] + bias[n], 3x-bf16 split.
// CTA: 128x128 tile, 256 threads, 8 warps (4x2), warp tile 32x64.
// BK=32, swizzled smem (no padding), 3 stages = 96KB -> 2 CTAs/SM.
// MODE: 0 = fp32 row-major out; 1 = Q fp16 scaled (B,H,T,D);
//       2 = K fp16 (B,H,T,D);   3 = V fp16 transposed (B,H,D,T)
// ---------------------------------------------------------------------------
#define BK 32
#define TILE_B 8192                  // 128 rows * 64B
#define STAGE_B (4*TILE_B)           // Ah, Al, Bh, Bl = 32KB
#define STAGES 3
#define NCH (EMB/BK)                 // 32
#define GSMEM_BYTES (STAGES*STAGE_B) // 98304

template<int MODE>
__device__ __forceinline__ void hgemm_body(
    const __nv_bfloat16* __restrict__ Ah, const __nv_bfloat16* __restrict__ Al,
    const __nv_bfloat16* __restrict__ Bh, const __nv_bfloat16* __restrict__ Bl,
    const float* __restrict__ bias, void* __restrict__ dst)
{
    extern __shared__ __nv_bfloat16 smb[];
    const uint32_t sm0 = smem_u32(smb);

    const int tid  = threadIdx.x;
    const int wid  = tid >> 5;
    const int lane = tid & 31;
    const int m0 = blockIdx.x * 128;
    const int n0 = blockIdx.y * 128;
    const int warp_m = (wid >> 1) * 32;
    const int warp_n = (wid & 1) * 64;

    const __nv_bfloat16* gsrc[4];
    gsrc[0] = Ah + (size_t)m0 * EMB;
    gsrc[1] = Al + (size_t)m0 * EMB;
    gsrc[2] = Bh + (size_t)n0 * EMB;
    gsrc[3] = Bl + (size_t)n0 * EMB;

    // 4 tiles x 128 rows x 4 chunks of 16B; 2 chunk-writes per thread per tile
    auto load_chunk = [&](int stage, int kc) {
        const uint32_t sb = sm0 + (uint32_t)stage * STAGE_B;
#pragma unroll
        for (int t4 = 0; t4 < 4; t4++) {
#pragma unroll
            for (int e = 0; e < 2; e++) {
                const int idx = tid * 2 + e;      // 0..511
                const int row = idx >> 2;
                const int ch  = idx & 3;
                const void* src = gsrc[t4] + (size_t)row * EMB + kc * BK + ch * 8;
                cp_async16(sb + (uint32_t)t4 * TILE_B + sw64(row, ch), src);
            }
        }
        cp_commit();
    };

    float c[2][8][4];
#pragma unroll
    for (int mt = 0; mt < 2; mt++)
#pragma unroll
        for (int nt = 0; nt < 8; nt++)
#pragma unroll
            for (int e = 0; e < 4; e++) c[mt][nt][e] = 0.f;

    load_chunk(0, 0);
    load_chunk(1, 1);

    const int lr = lane & 15;
    const int lc = lane >> 4;

    for (int i = 0; i < NCH; i++) {
        if (i + 2 < NCH) { load_chunk((i + 2) % STAGES, i + 2); cp_wait<2>(); }
        else if (i + 1 < NCH) cp_wait<1>();
        else cp_wait<0>();
        __syncthreads();

        const uint32_t sb  = sm0 + (uint32_t)(i % STAGES) * STAGE_B;
        const uint32_t ahb = sb;
        const uint32_t alb = sb + TILE_B;
        const uint32_t bhb = sb + 2 * TILE_B;
        const uint32_t blb = sb + 3 * TILE_B;

#pragma unroll
        for (int kk = 0; kk < 2; kk++) {
            const int ch = kk * 2 + lc;
            uint32_t a_h[2][4], a_l[2][4];
#pragma unroll
            for (int mt = 0; mt < 2; mt++) {
                const uint32_t off = sw64(warp_m + mt * 16 + lr, ch);
                ldsm_x4(a_h[mt], ahb + off);
                ldsm_x4(a_l[mt], alb + off);
            }
#pragma unroll
            for (int nt2 = 0; nt2 < 4; nt2++) {
                uint32_t brh[4], brl[4];
                const uint32_t boff = sw64(warp_n + nt2 * 16 + lr, ch);
                ldsm_x4(brh, bhb + boff);
                ldsm_x4(brl, blb + boff);
                uint32_t b0h[2] = {brh[0], brh[2]};
                uint32_t b1h[2] = {brh[1], brh[3]};
                uint32_t b0l[2] = {brl[0], brl[2]};
                uint32_t b1l[2] = {brl[1], brl[3]};
#pragma unroll
                for (int mt = 0; mt < 2; mt++) {
                    mma16816(c[mt][2*nt2],   a_h[mt], b0h);
                    mma16816(c[mt][2*nt2],   a_h[mt], b0l);
                    mma16816(c[mt][2*nt2],   a_l[mt], b0h);
                    mma16816(c[mt][2*nt2+1], a_h[mt], b1h);
                    mma16816(c[mt][2*nt2+1], a_h[mt], b1l);
                    mma16816(c[mt][2*nt2+1], a_l[mt], b1h);
                }
            }
        }
        __syncthreads();
    }

    // --- epilogue
#pragma unroll
    for (int mt = 0; mt < 2; mt++) {
#pragma unroll
        for (int nt = 0; nt < 8; nt++) {
            const int n = n0 + warp_n + nt * 8 + (lane & 3) * 2;
            const float2 bb = *(const float2*)&bias[n];
#pragma unroll
            for (int half = 0; half < 2; half++) {
                const int m = m0 + warp_m + mt * 16 + (lane >> 2) + half * 8;
                float rx = c[mt][nt][half*2+0] + bb.x;
                float ry = c[mt][nt][half*2+1] + bb.y;
                if (MODE == 0) {
                    float2 r; r.x = rx; r.y = ry;
                    *(float2*)((float*)dst + (size_t)m * EMB + n) = r;
                } else {
                    const int bh = ((m >> 11) << 4) + (n >> 6);  // b*16 + h
                    const int t  = m & (SEQ - 1);
                    const int d  = n & 63;
                    if (MODE == 1) {
                        __half2 hv;
                        hv.x = __float2half_rn(rx * 0.125f);
                        hv.y = __float2half_rn(ry * 0.125f);
                        *(__half2*)((__half*)dst + ((size_t)bh * SEQ + t) * HDIM + d) = hv;
                    } else if (MODE == 2) {
                        __half2 hv;
                        hv.x = __float2half_rn(rx);
                        hv.y = __float2half_rn(ry);
                        *(__half2*)((__half*)dst + ((size_t)bh * SEQ + t) * HDIM + d) = hv;
                    } else {
                        __half* p = (__half*)dst + ((size_t)bh * HDIM + d) * SEQ + t;
                        p[0]   = __float2half_rn(rx);
                        p[SEQ] = __float2half_rn(ry);
                    }
                }
            }
        }
    }
}

__global__ void __launch_bounds__(256, 2) qkv_hgemm_kernel(
    const float* __restrict__ bq, const float* __restrict__ bk, const float* __restrict__ bv)
{
    const int z = blockIdx.z;
    if (z == 0)
        hgemm_body<1>(g_xh, g_xl, g_wh, g_wl, bq, g_q16);
    else if (z == 1)
        hgemm_body<2>(g_xh, g_xl, g_wh + (size_t)EMB*EMB, g_wl + (size_t)EMB*EMB, bk, g_k16);
    else
        hgemm_body<3>(g_xh, g_xl, g_wh + (size_t)2*EMB*EMB, g_wl + (size_t)2*EMB*EMB, bv, g_v16);
}

__global__ void __launch_bounds__(256, 2) proj_hgemm_kernel(
    const float* __restrict__ bo, float* __restrict__ out)
{
    hgemm_body<0>(g_ah, g_al, g_wh + (size_t)3*EMB*EMB, g_wl + (size_t)3*EMB*EMB, bo, out);
}

// ---------------------------------------------------------------------------
// HMMA causal flash attention, all-fp16 operands, fp32 accum.
// CTA: 128 queries x one (b,h). 8 warps, each owns 16 query rows.
// KV tiles of 64, double-buffered cp.async, SW128 swizzled smem (48KB).
// ---------------------------------------------------------------------------
#define Q_BYTES (128*128)            // 16384
#define KV_STAGE_BYTES (2*64*128)    // K + V per stage = 16384
#define ATTN_SMEM (Q_BYTES + 2*KV_STAGE_BYTES)   // 49152

__global__ void __launch_bounds__(256, 2) attn_hmma_kernel()
{
    extern __shared__ char smc[];
    const uint32_t sm0 = smem_u32(smc);

    const int tid  = threadIdx.x;
    const int wid  = tid >> 5;
    const int lane = tid & 31;
    const int qt = (gridDim.x - 1) - blockIdx.x;   // longest first
    const int bh = blockIdx.y;

    const __half* qg = g_q16 + (size_t)bh * SEQ * HDIM;   // [t][d]
    const __half* kg = g_k16 + (size_t)bh * SEQ * HDIM;   // [t][d]
    const __half* vg = g_v16 + (size_t)bh * HDIM * SEQ;   // [d][t]

    // ---- issue Q tile load: 128 rows x 8 chunks of 16B
#pragma unroll
    for (int e = 0; e < 4; e++) {
        const int idx = tid * 4 + e;        // 0..1023
        const int row = idx >> 3;
        const int ch  = idx & 7;
        cp_async16(sm0 + sw128(row, ch),
                   qg + ((size_t)qt * 128 + row) * HDIM + ch * 8);
    }
    cp_commit();

    auto load_kv = [&](int stage, int kt) {
        const uint32_t sb = sm0 + Q_BYTES + (uint32_t)stage * KV_STAGE_BYTES;
#pragma unroll
        for (int e = 0; e < 2; e++) {
            const int idx = tid * 2 + e;    // 0..511
            const int row = idx >> 3;
            const int ch  = idx & 7;
            cp_async16(sb + sw128(row, ch),
                       kg + ((size_t)kt * 64 + row) * HDIM + ch * 8);
            cp_async16(sb + 64*128 + sw128(row, ch),
                       vg + (size_t)row * SEQ + kt * 64 + ch * 8);
        }
        cp_commit();
    };

    const int nkv = 2 * qt + 2;
    load_kv(0, 0);

    cp_wait<1>();      // Q tile ready
    __syncthreads();

    const int lr = lane & 15;
    const int lc = lane >> 4;

    // ---- Q fragments (per warp, rows wid*16..+15), 4 k-steps
    uint32_t aq[4][4];
#pragma unroll
    for (int kk = 0; kk < 4; kk++)
        ldsm_x4(aq[kk], sm0 + sw128(wid*16 + lr, kk*2 + lc));

    float o[8][4];
#pragma unroll
    for (int nt = 0; nt < 8; nt++)
#pragma unroll
        for (int e = 0; e < 4; e++) o[nt][e] = 0.f;
    float m0r = -INFINITY, m1r = -INFINITY, l0r = 0.f, l1r = 0.f;

    const float LOG2E = 1.4426950408889634f;
    const int rbase = qt*128 + wid*16 + (lane >> 2);

    for (int kt = 0; kt < nkv; kt++) {
        if (kt + 1 < nkv) { load_kv((kt + 1) & 1, kt + 1); cp_wait<1>(); }
        else cp_wait<0>();
        __syncthreads();

        const uint32_t kb = sm0 + Q_BYTES + (uint32_t)(kt & 1) * KV_STAGE_BYTES;
        const uint32_t vb = kb + 64*128;

        // ---- S = Q K^T
        float s[8][4];
#pragma unroll
        for (int nt = 0; nt < 8; nt++)
#pragma unroll
            for (int e = 0; e < 4; e++) s[nt][e] = 0.f;

#pragma unroll
        for (int kk = 0; kk < 4; kk++) {
#pragma unroll
            for (int nt2 = 0; nt2 < 4; nt2++) {
                uint32_t br[4];
                ldsm_x4(br, kb + sw128(nt2*16 + lr, kk*2 + lc));
                uint32_t b0[2] = {br[0], br[2]};
                uint32_t b1[2] = {br[1], br[3]};
                mma16816h(s[2*nt2],   aq[kk], b0);
                mma16816h(s[2*nt2+1], aq[kk], b1);
            }
        }

        // ---- causal mask (diagonal region only)
        if (kt >= 2*qt) {
#pragma unroll
            for (int nt = 0; nt < 8; nt++) {
                const int col = kt*64 + nt*8 + (lane & 3)*2;
#pragma unroll
                for (int e = 0; e < 4; e++) {
                    const int cc = col + (e & 1);
                    const int rr = rbase + (e >> 1)*8;
                    if (cc > rr) s[nt][e] = -1e30f;
                }
            }
        }

        // ---- online softmax (rows r0 = lane>>2, r1 = r0+8; quad-lane reduce)
        float mx0 = -INFINITY, mx1 = -INFINITY;
#pragma unroll
        for (int nt = 0; nt < 8; nt++) {
            mx0 = fmaxf(mx0, fmaxf(s[nt][0], s[nt][1]));
            mx1 = fmaxf(mx1, fmaxf(s[nt][2], s[nt][3]));
        }
        mx0 = fmaxf(mx0, __shfl_xor_sync(0xffffffffu, mx0, 1));
        mx0 = fmaxf(mx0, __shfl_xor_sync(0xffffffffu, mx0, 2));
        mx1 = fmaxf(mx1, __shfl_xor_sync(0xffffffffu, mx1, 1));
        mx1 = fmaxf(mx1, __shfl_xor_sync(0xffffffffu, mx1, 2));
        const float mn0 = fmaxf(m0r, mx0);
        const float mn1 = fmaxf(m1r, mx1);
        const float a0 = exp2f((m0r - mn0) * LOG2E);
        const float a1 = exp2f((m1r - mn1) * LOG2E);
        m0r = mn0; m1r = mn1;

        float rs0 = 0.f, rs1 = 0.f;
#pragma unroll
        for (int nt = 0; nt < 8; nt++) {
            float p0 = exp2f((s[nt][0] - mn0) * LOG2E);
            float p1 = exp2f((s[nt][1] - mn0) * LOG2E);
            float p2 = exp2f((s[nt][2] - mn1) * LOG2E);
            float p3 = exp2f((s[nt][3] - mn1) * LOG2E);
            s[nt][0] = p0; s[nt][1] = p1; s[nt][2] = p2; s[nt][3] = p3;
            rs0 += p0 + p1; rs1 += p2 + p3;
        }
        rs0 += __shfl_xor_sync(0xffffffffu, rs0, 1);
        rs0 += __shfl_xor_sync(0xffffffffu, rs0, 2);
        rs1 += __shfl_xor_sync(0xffffffffu, rs1, 1);
        rs1 += __shfl_xor_sync(0xffffffffu, rs1, 2);
        l0r = l0r * a0 + rs0;
        l1r = l1r * a1 + rs1;

#pragma unroll
        for (int nt = 0; nt < 8; nt++) {
            o[nt][0] *= a0; o[nt][1] *= a0;
            o[nt][2] *= a1; o[nt][3] *= a1;
        }

        // ---- P fragments (C-frag -> A-frag identity)
        uint32_t pf[4][4];
#pragma unroll
        for (int kk = 0; kk < 4; kk++) {
            pf[kk][0] = pack_h2(s[2*kk][0],   s[2*kk][1]);
            pf[kk][1] = pack_h2(s[2*kk][2],   s[2*kk][3]);
            pf[kk][2] = pack_h2(s[2*kk+1][0], s[2*kk+1][1]);
            pf[kk][3] = pack_h2(s[2*kk+1][2], s[2*kk+1][3]);
        }

        // ---- O += P V   (V^T in smem: [d][kv])
#pragma unroll
        for (int kk = 0; kk < 4; kk++) {
#pragma unroll
            for (int nt2 = 0; nt2 < 4; nt2++) {
                uint32_t br[4];
                ldsm_x4(br, vb + sw128(nt2*16 + lr, kk*2 + lc));
                uint32_t b0[2] = {br[0], br[2]};
                uint32_t b1[2] = {br[1], br[3]};
                mma16816h(o[2*nt2],   pf[kk], b0);
                mma16816h(o[2*nt2+1], pf[kk], b1);
            }
        }
        __syncthreads();
    }

    // ---- finalize: write bf16 hi/lo into (B,T,C)
    const float inv0 = 1.f / l0r;
    const float inv1 = 1.f / l1r;
    const int b = bh >> 4;
    const int h = bh & 15;
    const int t0 = qt*128 + wid*16 + (lane >> 2);
#pragma unroll
    for (int nt = 0; nt < 8; nt++) {
        const int d = nt*8 + (lane & 3)*2;
#pragma unroll
        for (int half = 0; half < 2; half++) {
            const int t = t0 + half*8;
            const float inv = half ? inv1 : inv0;
            const float vx = o[nt][half*2+0] * inv;
            const float vy = o[nt][half*2+1] * inv;
            __nv_bfloat16 hx = __float2bfloat16(vx);
            __nv_bfloat16 hy = __float2bfloat16(vy);
            __nv_bfloat162 hv; hv.x = hx; hv.y = hy;
            __nv_bfloat162 lv;
            lv.x = __float2bfloat16(vx - __bfloat162float(hx));
            lv.y = __float2bfloat16(vy - __bfloat162float(hy));
            const size_t off = ((size_t)(b*SEQ + t)) * EMB + h*HDIM + d;
            *(__nv_bfloat162*)&g_ah[off] = hv;
            *(__nv_bfloat162*)&g_al[off] = lv;
        }
    }
}

// ---------------------------------------------------------------------------
extern "C" void kernel_launch(void* const* d_in, const int* in_sizes, int n_in,
                              void* d_out, int out_size)
{
    const float* x   = (const float*)d_in[0];
    const float* W_q = (const float*)d_in[1];
    const float* b_q = (const float*)d_in[2];
    const float* W_k = (const float*)d_in[3];
    const float* b_k = (const float*)d_in[4];
    const float* W_v = (const float*)d_in[5];
    const float* b_v = (const float*)d_in[6];
    const float* W_o = (const float*)d_in[7];
    const float* b_o = (const float*)d_in[8];
    float* out = (float*)d_out;

    static bool attr_set = false;
    if (!attr_set) {
        cudaFuncSetAttribute(attn_hmma_kernel,
                             cudaFuncAttributeMaxDynamicSharedMemorySize, ATTN_SMEM);
        cudaFuncSetAttribute(qkv_hgemm_kernel,
                             cudaFuncAttributeMaxDynamicSharedMemorySize, GSMEM_BYTES);
        cudaFuncSetAttribute(proj_hgemm_kernel,
                             cudaFuncAttributeMaxDynamicSharedMemorySize, GSMEM_BYTES);
        attr_set = true;
    }

    __nv_bfloat16 *xh, *xl, *wh, *wl;
    cudaGetSymbolAddress((void**)&xh, g_xh);
    cudaGetSymbolAddress((void**)&xl, g_xl);
    cudaGetSymbolAddress((void**)&wh, g_wh);
    cudaGetSymbolAddress((void**)&wl, g_wl);

    // 1) split conversions (x and 4 weights)
    {
        int n4 = MROWS * EMB / 4;
        convert_split_kernel<<<(n4 + 255) / 256, 256>>>(x, xh, xl, n4);
        int w4 = EMB * EMB / 4;
        convert_split_kernel<<<(w4 + 255) / 256, 256>>>(W_q, wh + 0*(size_t)EMB*EMB, wl + 0*(size_t)EMB*EMB, w4);
        convert_split_kernel<<<(w4 + 255) / 256, 256>>>(W_k, wh + 1*(size_t)EMB*EMB, wl + 1*(size_t)EMB*EMB, w4);
        convert_split_kernel<<<(w4 + 255) / 256, 256>>>(W_v, wh + 2*(size_t)EMB*EMB, wl + 2*(size_t)EMB*EMB, w4);
        convert_split_kernel<<<(w4 + 255) / 256, 256>>>(W_o, wh + 3*(size_t)EMB*EMB, wl + 3*(size_t)EMB*EMB, w4);
    }

    // 2) QKV projections (writes fp16 q/k and transposed v)
    dim3 gqkv(MROWS/128, EMB/128, 3);
    qkv_hgemm_kernel<<<gqkv, 256, GSMEM_BYTES>>>(b_q, b_k, b_v);

    // 3) HMMA flash attention (writes bf16 hi/lo attention output)
    dim3 gattn(SEQ/128, BATCH*HEADS);
    attn_hmma_kernel<<<gattn, 256, ATTN_SMEM>>>();

    // 4) output projection
    dim3 gproj(MROWS/128, EMB/128);
    proj_hgemm_kernel<<<gproj, 256, GSMEM_BYTES>>>(b_o, out);
}

// round 6
// speedup vs baseline: 5.8914x; 1.8518x over previous
#include <cuda_runtime.h>
#include <cuda_bf16.h>
#include <cuda_fp16.h>
#include <cstdint>
#include <cmath>

// Problem constants
#define BATCH 2
#define SEQ   2048
#define EMB   1024
#define HEADS 16
#define HDIM  64
#define MROWS (BATCH*SEQ)   // 4096

// Scratch (device globals; no allocation allowed)
__device__ __half g_x16[MROWS*EMB];              // x as fp16 (B*T, C)
__device__ __half g_w16[4*EMB*EMB];              // Wq,Wk,Wv,Wo as fp16
__device__ __half g_q16[BATCH*HEADS*SEQ*HDIM];   // (B,H,T,D), pre-scaled by 0.125
__device__ __half g_k16[BATCH*HEADS*SEQ*HDIM];   // (B,H,T,D)
__device__ __half g_v16[BATCH*HEADS*SEQ*HDIM];   // (B,H,D,T)  transposed!
__device__ __half g_a16[MROWS*EMB];              // attention out (B,T,C)

// ---------------------------------------------------------------------------
// PTX helpers (family-level: sm_80+ instructions only)
// ---------------------------------------------------------------------------
__device__ __forceinline__ uint32_t smem_u32(const void* p) {
    uint32_t a;
    asm("{ .reg .u64 t; cvta.to.shared.u64 t, %1; cvt.u32.u64 %0, t; }" : "=r"(a) : "l"(p));
    return a;
}
__device__ __forceinline__ void cp_async16(uint32_t dst, const void* src) {
    asm volatile("cp.async.cg.shared.global [%0], [%1], 16;" :: "r"(dst), "l"(src));
}
__device__ __forceinline__ void cp_commit() {
    asm volatile("cp.async.commit_group;" ::: "memory");
}
template<int N>
__device__ __forceinline__ void cp_wait() {
    asm volatile("cp.async.wait_group %0;" :: "n"(N) : "memory");
}
__device__ __forceinline__ void ldsm_x4(uint32_t* r, uint32_t addr) {
    asm volatile("ldmatrix.sync.aligned.m8n8.x4.shared.b16 {%0,%1,%2,%3}, [%4];"
                 : "=r"(r[0]), "=r"(r[1]), "=r"(r[2]), "=r"(r[3]) : "r"(addr));
}
__device__ __forceinline__ void mma16816h(float* c, const uint32_t* a, const uint32_t* b) {
    asm volatile(
        "mma.sync.aligned.m16n8k16.row.col.f32.f16.f16.f32 "
        "{%0,%1,%2,%3}, {%4,%5,%6,%7}, {%8,%9}, {%0,%1,%2,%3};"
        : "+f"(c[0]), "+f"(c[1]), "+f"(c[2]), "+f"(c[3])
        : "r"(a[0]), "r"(a[1]), "r"(a[2]), "r"(a[3]), "r"(b[0]), "r"(b[1]));
}
// pack two fp32 -> f16x2 (lo in low half)
__device__ __forceinline__ uint32_t pack_h2(float lo, float hi) {
    uint32_t r;
    asm("cvt.rn.f16x2.f32 %0, %1, %2;" : "=r"(r) : "f"(hi), "f"(lo));
    return r;
}
// Swizzle for exact 128B rows (64 fp16). row any, ch 0..7 (16B chunks).
__device__ __forceinline__ uint32_t sw128(int row, int ch) {
    return (uint32_t)(row * 128 + ((ch ^ (row & 7)) * 16));
}

// ---------------------------------------------------------------------------
// fp32 -> fp16 convert
// ---------------------------------------------------------------------------
__global__ void __launch_bounds__(256) convert_half_kernel(
    const float* __restrict__ src, __half* __restrict__ dst, int n4)
{
    int i = blockIdx.x * blockDim.x + threadIdx.x;
    if (i >= n4) return;
    float4 v = ((const float4*)src)[i];
    uint2 r;
    r.x = pack_h2(v.x, v.y);
    r.y = pack_h2(v.z, v.w);
    ((uint2*)dst)[i] = r;
}

// ---------------------------------------------------------------------------
// fp16 HMMA GEMM: out[m][n] = sum_k A[m][k]*W[n][k] + bias[n].
// CTA: 128x128 tile, 256 threads, 8 warps (4x2), warp tile 32x64.
// BK=64, SW128 swizzled smem, 3 stages x 32KB = 96KB -> 2 CTAs/SM.
// MODE: 0 = fp32 row-major out; 1 = Q fp16 scaled (B,H,T,D);
//       2 = K fp16 (B,H,T,D);   3 = V fp16 transposed (B,H,D,T)
// ---------------------------------------------------------------------------
#define BK 64
#define TILE_B (128*128)             // 16 KB (128 rows x 64 fp16)
#define STAGE_B (2*TILE_B)           // A + B = 32 KB
#define STAGES 3
#define NCH (EMB/BK)                 // 16
#define GSMEM_BYTES (STAGES*STAGE_B) // 98304

template<int MODE>
__device__ __forceinline__ void hgemm_body(
    const __half* __restrict__ A, const __half* __restrict__ B,
    const float* __restrict__ bias, void* __restrict__ dst)
{
    extern __shared__ __half smb[];
    const uint32_t sm0 = smem_u32(smb);

    const int tid  = threadIdx.x;
    const int wid  = tid >> 5;
    const int lane = tid & 31;
    const int m0 = blockIdx.x * 128;
    const int n0 = blockIdx.y * 128;
    const int warp_m = (wid >> 1) * 32;
    const int warp_n = (wid & 1) * 64;

    const __half* asrc = A + (size_t)m0 * EMB;
    const __half* bsrc = B + (size_t)n0 * EMB;

    // 2 tiles x 128 rows x 8 chunks of 16B; 4 chunk-writes per thread per tile
    auto load_chunk = [&](int stage, int kc) {
        const uint32_t sb = sm0 + (uint32_t)stage * STAGE_B;
#pragma unroll
        for (int e = 0; e < 4; e++) {
            const int idx = tid * 4 + e;      // 0..1023
            const int row = idx >> 3;
            const int ch  = idx & 7;
            cp_async16(sb + sw128(row, ch),
                       asrc + (size_t)row * EMB + kc * BK + ch * 8);
            cp_async16(sb + TILE_B + sw128(row, ch),
                       bsrc + (size_t)row * EMB + kc * BK + ch * 8);
        }
        cp_commit();
    };

    float c[2][8][4];
#pragma unroll
    for (int mt = 0; mt < 2; mt++)
#pragma unroll
        for (int nt = 0; nt < 8; nt++)
#pragma unroll
            for (int e = 0; e < 4; e++) c[mt][nt][e] = 0.f;

    load_chunk(0, 0);
    load_chunk(1, 1);

    const int lr = lane & 15;
    const int lc = lane >> 4;

    for (int i = 0; i < NCH; i++) {
        if (i + 2 < NCH) { load_chunk((i + 2) % STAGES, i + 2); cp_wait<2>(); }
        else if (i + 1 < NCH) cp_wait<1>();
        else cp_wait<0>();
        __syncthreads();

        const uint32_t ab = sm0 + (uint32_t)(i % STAGES) * STAGE_B;
        const uint32_t bb = ab + TILE_B;

#pragma unroll
        for (int kk = 0; kk < 4; kk++) {
            const int ch = kk * 2 + lc;
            uint32_t a[2][4];
#pragma unroll
            for (int mt = 0; mt < 2; mt++)
                ldsm_x4(a[mt], ab + sw128(warp_m + mt * 16 + lr, ch));
#pragma unroll
            for (int nt2 = 0; nt2 < 4; nt2++) {
                uint32_t br[4];
                ldsm_x4(br, bb + sw128(warp_n + nt2 * 16 + lr, ch));
                uint32_t b0[2] = {br[0], br[2]};
                uint32_t b1[2] = {br[1], br[3]};
#pragma unroll
                for (int mt = 0; mt < 2; mt++) {
                    mma16816h(c[mt][2*nt2],   a[mt], b0);
                    mma16816h(c[mt][2*nt2+1], a[mt], b1);
                }
            }
        }
        __syncthreads();
    }

    // --- epilogue
#pragma unroll
    for (int mt = 0; mt < 2; mt++) {
#pragma unroll
        for (int nt = 0; nt < 8; nt++) {
            const int n = n0 + warp_n + nt * 8 + (lane & 3) * 2;
            const float2 bb2 = *(const float2*)&bias[n];
#pragma unroll
            for (int half = 0; half < 2; half++) {
                const int m = m0 + warp_m + mt * 16 + (lane >> 2) + half * 8;
                float rx = c[mt][nt][half*2+0] + bb2.x;
                float ry = c[mt][nt][half*2+1] + bb2.y;
                if (MODE == 0) {
                    float2 r; r.x = rx; r.y = ry;
                    *(float2*)((float*)dst + (size_t)m * EMB + n) = r;
                } else {
                    const int bh = ((m >> 11) << 4) + (n >> 6);  // b*16 + h
                    const int t  = m & (SEQ - 1);
                    const int d  = n & 63;
                    if (MODE == 1) {
                        __half2 hv;
                        hv.x = __float2half_rn(rx * 0.125f);
                        hv.y = __float2half_rn(ry * 0.125f);
                        *(__half2*)((__half*)dst + ((size_t)bh * SEQ + t) * HDIM + d) = hv;
                    } else if (MODE == 2) {
                        __half2 hv;
                        hv.x = __float2half_rn(rx);
                        hv.y = __float2half_rn(ry);
                        *(__half2*)((__half*)dst + ((size_t)bh * SEQ + t) * HDIM + d) = hv;
                    } else {
                        __half* p = (__half*)dst + ((size_t)bh * HDIM + d) * SEQ + t;
                        p[0]   = __float2half_rn(rx);
                        p[SEQ] = __float2half_rn(ry);
                    }
                }
            }
        }
    }
}

__global__ void __launch_bounds__(256, 2) qkv_hgemm_kernel(
    const float* __restrict__ bq, const float* __restrict__ bk, const float* __restrict__ bv)
{
    const int z = blockIdx.z;
    if (z == 0)
        hgemm_body<1>(g_x16, g_w16, bq, g_q16);
    else if (z == 1)
        hgemm_body<2>(g_x16, g_w16 + (size_t)EMB*EMB, bk, g_k16);
    else
        hgemm_body<3>(g_x16, g_w16 + (size_t)2*EMB*EMB, bv, g_v16);
}

__global__ void __launch_bounds__(256, 2) proj_hgemm_kernel(
    const float* __restrict__ bo, float* __restrict__ out)
{
    hgemm_body<0>(g_a16, g_w16 + (size_t)3*EMB*EMB, bo, out);
}

// ---------------------------------------------------------------------------
// HMMA causal flash attention, all-fp16 operands, fp32 accum.
// CTA: 128 queries x one (b,h). 8 warps, each owns 16 query rows.
// KV tiles of 64, double-buffered cp.async, SW128 swizzled smem (48KB).
// ---------------------------------------------------------------------------
#define Q_BYTES (128*128)            // 16384
#define KV_STAGE_BYTES (2*64*128)    // K + V per stage = 16384
#define ATTN_SMEM (Q_BYTES + 2*KV_STAGE_BYTES)   // 49152

__global__ void __launch_bounds__(256, 2) attn_hmma_kernel()
{
    extern __shared__ char smc[];
    const uint32_t sm0 = smem_u32(smc);

    const int tid  = threadIdx.x;
    const int wid  = tid >> 5;
    const int lane = tid & 31;
    const int qt = (gridDim.x - 1) - blockIdx.x;   // longest first
    const int bh = blockIdx.y;

    const __half* qg = g_q16 + (size_t)bh * SEQ * HDIM;   // [t][d]
    const __half* kg = g_k16 + (size_t)bh * SEQ * HDIM;   // [t][d]
    const __half* vg = g_v16 + (size_t)bh * HDIM * SEQ;   // [d][t]

    // ---- issue Q tile load: 128 rows x 8 chunks of 16B
#pragma unroll
    for (int e = 0; e < 4; e++) {
        const int idx = tid * 4 + e;        // 0..1023
        const int row = idx >> 3;
        const int ch  = idx & 7;
        cp_async16(sm0 + sw128(row, ch),
                   qg + ((size_t)qt * 128 + row) * HDIM + ch * 8);
    }
    cp_commit();

    auto load_kv = [&](int stage, int kt) {
        const uint32_t sb = sm0 + Q_BYTES + (uint32_t)stage * KV_STAGE_BYTES;
#pragma unroll
        for (int e = 0; e < 2; e++) {
            const int idx = tid * 2 + e;    // 0..511
            const int row = idx >> 3;
            const int ch  = idx & 7;
            cp_async16(sb + sw128(row, ch),
                       kg + ((size_t)kt * 64 + row) * HDIM + ch * 8);
            cp_async16(sb + 64*128 + sw128(row, ch),
                       vg + (size_t)row * SEQ + kt * 64 + ch * 8);
        }
        cp_commit();
    };

    const int nkv = 2 * qt + 2;
    load_kv(0, 0);

    cp_wait<1>();      // Q tile ready
    __syncthreads();

    const int lr = lane & 15;
    const int lc = lane >> 4;

    // ---- Q fragments (per warp, rows wid*16..+15), 4 k-steps
    uint32_t aq[4][4];
#pragma unroll
    for (int kk = 0; kk < 4; kk++)
        ldsm_x4(aq[kk], sm0 + sw128(wid*16 + lr, kk*2 + lc));

    float o[8][4];
#pragma unroll
    for (int nt = 0; nt < 8; nt++)
#pragma unroll
        for (int e = 0; e < 4; e++) o[nt][e] = 0.f;
    float m0r = -INFINITY, m1r = -INFINITY, l0r = 0.f, l1r = 0.f;

    const float LOG2E = 1.4426950408889634f;
    const int rbase = qt*128 + wid*16 + (lane >> 2);

    for (int kt = 0; kt < nkv; kt++) {
        if (kt + 1 < nkv) { load_kv((kt + 1) & 1, kt + 1); cp_wait<1>(); }
        else cp_wait<0>();
        __syncthreads();

        const uint32_t kb = sm0 + Q_BYTES + (uint32_t)(kt & 1) * KV_STAGE_BYTES;
        const uint32_t vb = kb + 64*128;

        // ---- S = Q K^T
        float s[8][4];
#pragma unroll
        for (int nt = 0; nt < 8; nt++)
#pragma unroll
            for (int e = 0; e < 4; e++) s[nt][e] = 0.f;

#pragma unroll
        for (int kk = 0; kk < 4; kk++) {
#pragma unroll
            for (int nt2 = 0; nt2 < 4; nt2++) {
                uint32_t br[4];
                ldsm_x4(br, kb + sw128(nt2*16 + lr, kk*2 + lc));
                uint32_t b0[2] = {br[0], br[2]};
                uint32_t b1[2] = {br[1], br[3]};
                mma16816h(s[2*nt2],   aq[kk], b0);
                mma16816h(s[2*nt2+1], aq[kk], b1);
            }
        }

        // ---- causal mask (diagonal region only)
        if (kt >= 2*qt) {
#pragma unroll
            for (int nt = 0; nt < 8; nt++) {
                const int col = kt*64 + nt*8 + (lane & 3)*2;
#pragma unroll
                for (int e = 0; e < 4; e++) {
                    const int cc = col + (e & 1);
                    const int rr = rbase + (e >> 1)*8;
                    if (cc > rr) s[nt][e] = -1e30f;
                }
            }
        }

        // ---- online softmax (rows r0 = lane>>2, r1 = r0+8; quad-lane reduce)
        float mx0 = -INFINITY, mx1 = -INFINITY;
#pragma unroll
        for (int nt = 0; nt < 8; nt++) {
            mx0 = fmaxf(mx0, fmaxf(s[nt][0], s[nt][1]));
            mx1 = fmaxf(mx1, fmaxf(s[nt][2], s[nt][3]));
        }
        mx0 = fmaxf(mx0, __shfl_xor_sync(0xffffffffu, mx0, 1));
        mx0 = fmaxf(mx0, __shfl_xor_sync(0xffffffffu, mx0, 2));
        mx1 = fmaxf(mx1, __shfl_xor_sync(0xffffffffu, mx1, 1));
        mx1 = fmaxf(mx1, __shfl_xor_sync(0xffffffffu, mx1, 2));
        const float mn0 = fmaxf(m0r, mx0);
        const float mn1 = fmaxf(m1r, mx1);
        const float a0 = exp2f((m0r - mn0) * LOG2E);
        const float a1 = exp2f((m1r - mn1) * LOG2E);
        m0r = mn0; m1r = mn1;

        float rs0 = 0.f, rs1 = 0.f;
#pragma unroll
        for (int nt = 0; nt < 8; nt++) {
            float p0 = exp2f((s[nt][0] - mn0) * LOG2E);
            float p1 = exp2f((s[nt][1] - mn0) * LOG2E);
            float p2 = exp2f((s[nt][2] - mn1) * LOG2E);
            float p3 = exp2f((s[nt][3] - mn1) * LOG2E);
            s[nt][0] = p0; s[nt][1] = p1; s[nt][2] = p2; s[nt][3] = p3;
            rs0 += p0 + p1; rs1 += p2 + p3;
        }
        rs0 += __shfl_xor_sync(0xffffffffu, rs0, 1);
        rs0 += __shfl_xor_sync(0xffffffffu, rs0, 2);
        rs1 += __shfl_xor_sync(0xffffffffu, rs1, 1);
        rs1 += __shfl_xor_sync(0xffffffffu, rs1, 2);
        l0r = l0r * a0 + rs0;
        l1r = l1r * a1 + rs1;

#pragma unroll
        for (int nt = 0; nt < 8; nt++) {
            o[nt][0] *= a0; o[nt][1] *= a0;
            o[nt][2] *= a1; o[nt][3] *= a1;
        }

        // ---- P fragments (C-frag -> A-frag identity)
        uint32_t pf[4][4];
#pragma unroll
        for (int kk = 0; kk < 4; kk++) {
            pf[kk][0] = pack_h2(s[2*kk][0],   s[2*kk][1]);
            pf[kk][1] = pack_h2(s[2*kk][2],   s[2*kk][3]);
            pf[kk][2] = pack_h2(s[2*kk+1][0], s[2*kk+1][1]);
            pf[kk][3] = pack_h2(s[2*kk+1][2], s[2*kk+1][3]);
        }

        // ---- O += P V   (V^T in smem: [d][kv])
#pragma unroll
        for (int kk = 0; kk < 4; kk++) {
#pragma unroll
            for (int nt2 = 0; nt2 < 4; nt2++) {
                uint32_t br[4];
                ldsm_x4(br, vb + sw128(nt2*16 + lr, kk*2 + lc));
                uint32_t b0[2] = {br[0], br[2]};
                uint32_t b1[2] = {br[1], br[3]};
                mma16816h(o[2*nt2],   pf[kk], b0);
                mma16816h(o[2*nt2+1], pf[kk], b1);
            }
        }
        __syncthreads();
    }

    // ---- finalize: write fp16 into (B,T,C)
    const float inv0 = 1.f / l0r;
    const float inv1 = 1.f / l1r;
    const int b = bh >> 4;
    const int h = bh & 15;
    const int t0 = qt*128 + wid*16 + (lane >> 2);
#pragma unroll
    for (int nt = 0; nt < 8; nt++) {
        const int d = nt*8 + (lane & 3)*2;
#pragma unroll
        for (int half = 0; half < 2; half++) {
            const int t = t0 + half*8;
            const float inv = half ? inv1 : inv0;
            const uint32_t hv = pack_h2(o[nt][half*2+0] * inv, o[nt][half*2+1] * inv);
            *(uint32_t*)&g_a16[((size_t)(b*SEQ + t)) * EMB + h*HDIM + d] = hv;
        }
    }
}

// ---------------------------------------------------------------------------
extern "C" void kernel_launch(void* const* d_in, const int* in_sizes, int n_in,
                              void* d_out, int out_size)
{
    const float* x   = (const float*)d_in[0];
    const float* W_q = (const float*)d_in[1];
    const float* b_q = (const float*)d_in[2];
    const float* W_k = (const float*)d_in[3];
    const float* b_k = (const float*)d_in[4];
    const float* W_v = (const float*)d_in[5];
    const float* b_v = (const float*)d_in[6];
    const float* W_o = (const float*)d_in[7];
    const float* b_o = (const float*)d_in[8];
    float* out = (float*)d_out;

    static bool attr_set = false;
    if (!attr_set) {
        cudaFuncSetAttribute(attn_hmma_kernel,
                             cudaFuncAttributeMaxDynamicSharedMemorySize, ATTN_SMEM);
        cudaFuncSetAttribute(qkv_hgemm_kernel,
                             cudaFuncAttributeMaxDynamicSharedMemorySize, GSMEM_BYTES);
        cudaFuncSetAttribute(proj_hgemm_kernel,
                             cudaFuncAttributeMaxDynamicSharedMemorySize, GSMEM_BYTES);
        attr_set = true;
    }

    __half *x16, *w16;
    cudaGetSymbolAddress((void**)&x16, g_x16);
    cudaGetSymbolAddress((void**)&w16, g_w16);

    // 1) fp16 conversions (x and 4 weights)
    {
        int n4 = MROWS * EMB / 4;
        convert_half_kernel<<<(n4 + 255) / 256, 256>>>(x, x16, n4);
        int w4 = EMB * EMB / 4;
        convert_half_kernel<<<(w4 + 255) / 256, 256>>>(W_q, w16 + 0*(size_t)EMB*EMB, w4);
        convert_half_kernel<<<(w4 + 255) / 256, 256>>>(W_k, w16 + 1*(size_t)EMB*EMB, w4);
        convert_half_kernel<<<(w4 + 255) / 256, 256>>>(W_v, w16 + 2*(size_t)EMB*EMB, w4);
        convert_half_kernel<<<(w4 + 255) / 256, 256>>>(W_o, w16 + 3*(size_t)EMB*EMB, w4);
    }

    // 2) QKV projections (writes fp16 q/k and transposed v)
    dim3 gqkv(MROWS/128, EMB/128, 3);
    qkv_hgemm_kernel<<<gqkv, 256, GSMEM_BYTES>>>(b_q, b_k, b_v);

    // 3) HMMA flash attention (writes fp16 attention output)
    dim3 gattn(SEQ/128, BATCH*HEADS);
    attn_hmma_kernel<<<gattn, 256, ATTN_SMEM>>>();

    // 4) output projection
    dim3 gproj(MROWS/128, EMB/128);
    proj_hgemm_kernel<<<gproj, 256, GSMEM_BYTES>>>(b_o, out);
}

// round 7
// speedup vs baseline: 6.0928x; 1.0342x over previous
#include <cuda_runtime.h>
#include <cuda_bf16.h>
#include <cuda_fp16.h>
#include <cstdint>
#include <cmath>

// Problem constants
#define BATCH 2
#define SEQ   2048
#define EMB   1024
#define HEADS 16
#define HDIM  64
#define MROWS (BATCH*SEQ)   // 4096

// Scratch (device globals; no allocation allowed)
__device__ __half g_x16[MROWS*EMB];              // x as fp16 (B*T, C)
__device__ __half g_w16[4*EMB*EMB];              // Wq,Wk,Wv,Wo as fp16
__device__ __half g_q16[BATCH*HEADS*SEQ*HDIM];   // (B,H,T,D), pre-scaled by 0.125
__device__ __half g_k16[BATCH*HEADS*SEQ*HDIM];   // (B,H,T,D)
__device__ __half g_v16[BATCH*HEADS*SEQ*HDIM];   // (B,H,D,T)  transposed!
__device__ __half g_a16[MROWS*EMB];              // attention out (B,T,C)

// ---------------------------------------------------------------------------
// PTX helpers (family-level: sm_80+ instructions only)
// ---------------------------------------------------------------------------
__device__ __forceinline__ uint32_t smem_u32(const void* p) {
    uint32_t a;
    asm("{ .reg .u64 t; cvta.to.shared.u64 t, %1; cvt.u32.u64 %0, t; }" : "=r"(a) : "l"(p));
    return a;
}
__device__ __forceinline__ void cp_async16(uint32_t dst, const void* src) {
    asm volatile("cp.async.cg.shared.global [%0], [%1], 16;" :: "r"(dst), "l"(src));
}
__device__ __forceinline__ void cp_commit() {
    asm volatile("cp.async.commit_group;" ::: "memory");
}
template<int N>
__device__ __forceinline__ void cp_wait() {
    asm volatile("cp.async.wait_group %0;" :: "n"(N) : "memory");
}
__device__ __forceinline__ void ldsm_x4(uint32_t* r, uint32_t addr) {
    asm volatile("ldmatrix.sync.aligned.m8n8.x4.shared.b16 {%0,%1,%2,%3}, [%4];"
                 : "=r"(r[0]), "=r"(r[1]), "=r"(r[2]), "=r"(r[3]) : "r"(addr));
}
__device__ __forceinline__ void mma16816h(float* c, const uint32_t* a, const uint32_t* b) {
    asm volatile(
        "mma.sync.aligned.m16n8k16.row.col.f32.f16.f16.f32 "
        "{%0,%1,%2,%3}, {%4,%5,%6,%7}, {%8,%9}, {%0,%1,%2,%3};"
        : "+f"(c[0]), "+f"(c[1]), "+f"(c[2]), "+f"(c[3])
        : "r"(a[0]), "r"(a[1]), "r"(a[2]), "r"(a[3]), "r"(b[0]), "r"(b[1]));
}
// pack two fp32 -> f16x2 (lo in low half)
__device__ __forceinline__ uint32_t pack_h2(float lo, float hi) {
    uint32_t r;
    asm("cvt.rn.f16x2.f32 %0, %1, %2;" : "=r"(r) : "f"(hi), "f"(lo));
    return r;
}
// Swizzle for exact 128B rows (64 fp16). row any, ch 0..7 (16B chunks).
__device__ __forceinline__ uint32_t sw128(int row, int ch) {
    return (uint32_t)(row * 128 + ((ch ^ (row & 7)) * 16));
}

// ---------------------------------------------------------------------------
// Fused fp32 -> fp16 convert: x (1M float4) then Wq,Wk,Wv,Wo (262144 each)
// ---------------------------------------------------------------------------
#define XN4 (MROWS*EMB/4)     // 1048576
#define WN4 (EMB*EMB/4)       // 262144
#define CVT_TOTAL (XN4 + 4*WN4)

__global__ void __launch_bounds__(256) convert_all_kernel(
    const float* __restrict__ x,
    const float* __restrict__ Wq, const float* __restrict__ Wk,
    const float* __restrict__ Wv, const float* __restrict__ Wo)
{
    const int i = blockIdx.x * blockDim.x + threadIdx.x;
    if (i >= CVT_TOTAL) return;
    const float* src;
    uint2* dst;
    int off;
    if (i < XN4) {
        src = x; dst = (uint2*)g_x16; off = i;
    } else {
        const int j = i - XN4;
        const int w = j >> 18;          // / WN4
        off = j & (WN4 - 1);
        src = (w == 0) ? Wq : (w == 1) ? Wk : (w == 2) ? Wv : Wo;
        dst = (uint2*)(g_w16 + (size_t)w * EMB * EMB);
    }
    float4 v = ((const float4*)src)[off];
    uint2 r;
    r.x = pack_h2(v.x, v.y);
    r.y = pack_h2(v.z, v.w);
    dst[off] = r;
}

// ---------------------------------------------------------------------------
// fp16 HMMA GEMM: out[m][n] = sum_k A[m][k]*W[n][k] + bias[n].
// CTA: 128x128 tile, 256 threads, 8 warps (4x2), warp tile 32x64.
// BK=64, SW128 swizzled smem, 3 stages x 32KB = 96KB -> 2 CTAs/SM.
// Single __syncthreads per chunk (load issued post-sync, 3-stage safe).
// MODE: 0 = fp32 row-major out; 1 = Q fp16 scaled (B,H,T,D);
//       2 = K fp16 (B,H,T,D);   3 = V fp16 transposed (B,H,D,T)
// ---------------------------------------------------------------------------
#define BK 64
#define TILE_B (128*128)             // 16 KB (128 rows x 64 fp16)
#define STAGE_B (2*TILE_B)           // A + B = 32 KB
#define STAGES 3
#define NCH (EMB/BK)                 // 16
#define GSMEM_BYTES (STAGES*STAGE_B) // 98304

template<int MODE>
__device__ __forceinline__ void hgemm_body(
    const __half* __restrict__ A, const __half* __restrict__ B,
    const float* __restrict__ bias, void* __restrict__ dst)
{
    extern __shared__ __half smb[];
    const uint32_t sm0 = smem_u32(smb);

    const int tid  = threadIdx.x;
    const int wid  = tid >> 5;
    const int lane = tid & 31;
    const int m0 = blockIdx.x * 128;
    const int n0 = blockIdx.y * 128;
    const int warp_m = (wid >> 1) * 32;
    const int warp_n = (wid & 1) * 64;

    const __half* asrc = A + (size_t)m0 * EMB;
    const __half* bsrc = B + (size_t)n0 * EMB;

    // 2 tiles x 128 rows x 8 chunks of 16B; 4 chunk-writes per thread per tile
    auto load_chunk = [&](int stage, int kc) {
        const uint32_t sb = sm0 + (uint32_t)stage * STAGE_B;
#pragma unroll
        for (int e = 0; e < 4; e++) {
            const int idx = tid * 4 + e;      // 0..1023
            const int row = idx >> 3;
            const int ch  = idx & 7;
            cp_async16(sb + sw128(row, ch),
                       asrc + (size_t)row * EMB + kc * BK + ch * 8);
            cp_async16(sb + TILE_B + sw128(row, ch),
                       bsrc + (size_t)row * EMB + kc * BK + ch * 8);
        }
        cp_commit();
    };

    float c[2][8][4];
#pragma unroll
    for (int mt = 0; mt < 2; mt++)
#pragma unroll
        for (int nt = 0; nt < 8; nt++)
#pragma unroll
            for (int e = 0; e < 4; e++) c[mt][nt][e] = 0.f;

    load_chunk(0, 0);
    load_chunk(1, 1);

    const int lr = lane & 15;
    const int lc = lane >> 4;

    for (int i = 0; i < NCH; i++) {
        if (i < NCH - 1) cp_wait<1>(); else cp_wait<0>();
        __syncthreads();
        if (i + 2 < NCH) load_chunk((i + 2) % STAGES, i + 2);

        const uint32_t ab = sm0 + (uint32_t)(i % STAGES) * STAGE_B;
        const uint32_t bb = ab + TILE_B;

#pragma unroll
        for (int kk = 0; kk < 4; kk++) {
            const int ch = kk * 2 + lc;
            uint32_t a[2][4];
#pragma unroll
            for (int mt = 0; mt < 2; mt++)
                ldsm_x4(a[mt], ab + sw128(warp_m + mt * 16 + lr, ch));
#pragma unroll
            for (int nt2 = 0; nt2 < 4; nt2++) {
                uint32_t br[4];
                ldsm_x4(br, bb + sw128(warp_n + nt2 * 16 + lr, ch));
                uint32_t b0[2] = {br[0], br[2]};
                uint32_t b1[2] = {br[1], br[3]};
#pragma unroll
                for (int mt = 0; mt < 2; mt++) {
                    mma16816h(c[mt][2*nt2],   a[mt], b0);
                    mma16816h(c[mt][2*nt2+1], a[mt], b1);
                }
            }
        }
    }

    // --- epilogue
#pragma unroll
    for (int mt = 0; mt < 2; mt++) {
#pragma unroll
        for (int nt = 0; nt < 8; nt++) {
            const int n = n0 + warp_n + nt * 8 + (lane & 3) * 2;
            const float2 bb2 = *(const float2*)&bias[n];
#pragma unroll
            for (int half = 0; half < 2; half++) {
                const int m = m0 + warp_m + mt * 16 + (lane >> 2) + half * 8;
                float rx = c[mt][nt][half*2+0] + bb2.x;
                float ry = c[mt][nt][half*2+1] + bb2.y;
                if (MODE == 0) {
                    float2 r; r.x = rx; r.y = ry;
                    *(float2*)((float*)dst + (size_t)m * EMB + n) = r;
                } else {
                    const int bh = ((m >> 11) << 4) + (n >> 6);  // b*16 + h
                    const int t  = m & (SEQ - 1);
                    const int d  = n & 63;
                    if (MODE == 1) {
                        __half2 hv;
                        hv.x = __float2half_rn(rx * 0.125f);
                        hv.y = __float2half_rn(ry * 0.125f);
                        *(__half2*)((__half*)dst + ((size_t)bh * SEQ + t) * HDIM + d) = hv;
                    } else if (MODE == 2) {
                        __half2 hv;
                        hv.x = __float2half_rn(rx);
                        hv.y = __float2half_rn(ry);
                        *(__half2*)((__half*)dst + ((size_t)bh * SEQ + t) * HDIM + d) = hv;
                    } else {
                        __half* p = (__half*)dst + ((size_t)bh * HDIM + d) * SEQ + t;
                        p[0]   = __float2half_rn(rx);
                        p[SEQ] = __float2half_rn(ry);
                    }
                }
            }
        }
    }
}

__global__ void __launch_bounds__(256, 2) qkv_hgemm_kernel(
    const float* __restrict__ bq, const float* __restrict__ bk, const float* __restrict__ bv)
{
    const int z = blockIdx.z;
    if (z == 0)
        hgemm_body<1>(g_x16, g_w16, bq, g_q16);
    else if (z == 1)
        hgemm_body<2>(g_x16, g_w16 + (size_t)EMB*EMB, bk, g_k16);
    else
        hgemm_body<3>(g_x16, g_w16 + (size_t)2*EMB*EMB, bv, g_v16);
}

__global__ void __launch_bounds__(256, 2) proj_hgemm_kernel(
    const float* __restrict__ bo, float* __restrict__ out)
{
    hgemm_body<0>(g_a16, g_w16 + (size_t)3*EMB*EMB, bo, out);
}

// ---------------------------------------------------------------------------
// HMMA causal flash attention, all-fp16 operands, fp32 accum.
// CTA: 128 queries x one (b,h). 8 warps, each owns 16 query rows.
// KV tiles of 64, 3-stage cp.async ring, single sync per iteration.
// smem: Q 16K + 3 x 16K = 64K -> 2 CTAs/SM.
// ---------------------------------------------------------------------------
#define Q_BYTES (128*128)            // 16384
#define KV_STAGE_BYTES (2*64*128)    // K + V per stage = 16384
#define KV_STAGES 3
#define ATTN_SMEM (Q_BYTES + KV_STAGES*KV_STAGE_BYTES)   // 65536

__global__ void __launch_bounds__(256, 2) attn_hmma_kernel()
{
    extern __shared__ char smc[];
    const uint32_t sm0 = smem_u32(smc);

    const int tid  = threadIdx.x;
    const int wid  = tid >> 5;
    const int lane = tid & 31;
    const int qt = (gridDim.x - 1) - blockIdx.x;   // longest first
    const int bh = blockIdx.y;

    const __half* qg = g_q16 + (size_t)bh * SEQ * HDIM;   // [t][d]
    const __half* kg = g_k16 + (size_t)bh * SEQ * HDIM;   // [t][d]
    const __half* vg = g_v16 + (size_t)bh * HDIM * SEQ;   // [d][t]

    // ---- issue Q tile load: 128 rows x 8 chunks of 16B (group 1)
#pragma unroll
    for (int e = 0; e < 4; e++) {
        const int idx = tid * 4 + e;        // 0..1023
        const int row = idx >> 3;
        const int ch  = idx & 7;
        cp_async16(sm0 + sw128(row, ch),
                   qg + ((size_t)qt * 128 + row) * HDIM + ch * 8);
    }
    cp_commit();

    auto load_kv = [&](int stage, int kt) {
        const uint32_t sb = sm0 + Q_BYTES + (uint32_t)stage * KV_STAGE_BYTES;
#pragma unroll
        for (int e = 0; e < 2; e++) {
            const int idx = tid * 2 + e;    // 0..511
            const int row = idx >> 3;
            const int ch  = idx & 7;
            cp_async16(sb + sw128(row, ch),
                       kg + ((size_t)kt * 64 + row) * HDIM + ch * 8);
            cp_async16(sb + 64*128 + sw128(row, ch),
                       vg + (size_t)row * SEQ + kt * 64 + ch * 8);
        }
        cp_commit();
    };

    const int nkv = 2 * qt + 2;
    load_kv(0, 0);                 // group 2
    if (nkv > 1) load_kv(1, 1);    // group 3

    // Q ready when <=2 groups pending
    cp_wait<2>();
    __syncthreads();

    const int lr = lane & 15;
    const int lc = lane >> 4;

    // ---- Q fragments (per warp, rows wid*16..+15), 4 k-steps
    uint32_t aq[4][4];
#pragma unroll
    for (int kk = 0; kk < 4; kk++)
        ldsm_x4(aq[kk], sm0 + sw128(wid*16 + lr, kk*2 + lc));

    float o[8][4];
#pragma unroll
    for (int nt = 0; nt < 8; nt++)
#pragma unroll
        for (int e = 0; e < 4; e++) o[nt][e] = 0.f;
    float m0r = -INFINITY, m1r = -INFINITY, l0r = 0.f, l1r = 0.f;

    const float LOG2E = 1.4426950408889634f;
    const int rbase = qt*128 + wid*16 + (lane >> 2);

    for (int kt = 0; kt < nkv; kt++) {
        if (kt < nkv - 1) cp_wait<1>(); else cp_wait<0>();
        __syncthreads();
        if (kt + 2 < nkv) load_kv((kt + 2) % KV_STAGES, kt + 2);

        const uint32_t kb = sm0 + Q_BYTES + (uint32_t)(kt % KV_STAGES) * KV_STAGE_BYTES;
        const uint32_t vb = kb + 64*128;

        // ---- S = Q K^T
        float s[8][4];
#pragma unroll
        for (int nt = 0; nt < 8; nt++)
#pragma unroll
            for (int e = 0; e < 4; e++) s[nt][e] = 0.f;

#pragma unroll
        for (int kk = 0; kk < 4; kk++) {
#pragma unroll
            for (int nt2 = 0; nt2 < 4; nt2++) {
                uint32_t br[4];
                ldsm_x4(br, kb + sw128(nt2*16 + lr, kk*2 + lc));
                uint32_t b0[2] = {br[0], br[2]};
                uint32_t b1[2] = {br[1], br[3]};
                mma16816h(s[2*nt2],   aq[kk], b0);
                mma16816h(s[2*nt2+1], aq[kk], b1);
            }
        }

        // ---- causal mask (diagonal region only)
        if (kt >= 2*qt) {
#pragma unroll
            for (int nt = 0; nt < 8; nt++) {
                const int col = kt*64 + nt*8 + (lane & 3)*2;
#pragma unroll
                for (int e = 0; e < 4; e++) {
                    const int cc = col + (e & 1);
                    const int rr = rbase + (e >> 1)*8;
                    if (cc > rr) s[nt][e] = -1e30f;
                }
            }
        }

        // ---- online softmax (rows r0 = lane>>2, r1 = r0+8; quad-lane reduce)
        float mx0 = -INFINITY, mx1 = -INFINITY;
#pragma unroll
        for (int nt = 0; nt < 8; nt++) {
            mx0 = fmaxf(mx0, fmaxf(s[nt][0], s[nt][1]));
            mx1 = fmaxf(mx1, fmaxf(s[nt][2], s[nt][3]));
        }
        mx0 = fmaxf(mx0, __shfl_xor_sync(0xffffffffu, mx0, 1));
        mx0 = fmaxf(mx0, __shfl_xor_sync(0xffffffffu, mx0, 2));
        mx1 = fmaxf(mx1, __shfl_xor_sync(0xffffffffu, mx1, 1));
        mx1 = fmaxf(mx1, __shfl_xor_sync(0xffffffffu, mx1, 2));
        const float mn0 = fmaxf(m0r, mx0);
        const float mn1 = fmaxf(m1r, mx1);
        const float a0 = exp2f((m0r - mn0) * LOG2E);
        const float a1 = exp2f((m1r - mn1) * LOG2E);
        m0r = mn0; m1r = mn1;

        float rs0 = 0.f, rs1 = 0.f;
#pragma unroll
        for (int nt = 0; nt < 8; nt++) {
            float p0 = exp2f((s[nt][0] - mn0) * LOG2E);
            float p1 = exp2f((s[nt][1] - mn0) * LOG2E);
            float p2 = exp2f((s[nt][2] - mn1) * LOG2E);
            float p3 = exp2f((s[nt][3] - mn1) * LOG2E);
            s[nt][0] = p0; s[nt][1] = p1; s[nt][2] = p2; s[nt][3] = p3;
            rs0 += p0 + p1; rs1 += p2 + p3;
        }
        rs0 += __shfl_xor_sync(0xffffffffu, rs0, 1);
        rs0 += __shfl_xor_sync(0xffffffffu, rs0, 2);
        rs1 += __shfl_xor_sync(0xffffffffu, rs1, 1);
        rs1 += __shfl_xor_sync(0xffffffffu, rs1, 2);
        l0r = l0r * a0 + rs0;
        l1r = l1r * a1 + rs1;

#pragma unroll
        for (int nt = 0; nt < 8; nt++) {
            o[nt][0] *= a0; o[nt][1] *= a0;
            o[nt][2] *= a1; o[nt][3] *= a1;
        }

        // ---- P fragments (C-frag -> A-frag identity)
        uint32_t pf[4][4];
#pragma unroll
        for (int kk = 0; kk < 4; kk++) {
            pf[kk][0] = pack_h2(s[2*kk][0],   s[2*kk][1]);
            pf[kk][1] = pack_h2(s[2*kk][2],   s[2*kk][3]);
            pf[kk][2] = pack_h2(s[2*kk+1][0], s[2*kk+1][1]);
            pf[kk][3] = pack_h2(s[2*kk+1][2], s[2*kk+1][3]);
        }

        // ---- O += P V   (V^T in smem: [d][kv])
#pragma unroll
        for (int kk = 0; kk < 4; kk++) {
#pragma unroll
            for (int nt2 = 0; nt2 < 4; nt2++) {
                uint32_t br[4];
                ldsm_x4(br, vb + sw128(nt2*16 + lr, kk*2 + lc));
                uint32_t b0[2] = {br[0], br[2]};
                uint32_t b1[2] = {br[1], br[3]};
                mma16816h(o[2*nt2],   pf[kk], b0);
                mma16816h(o[2*nt2+1], pf[kk], b1);
            }
        }
    }

    // ---- finalize: write fp16 into (B,T,C)
    const float inv0 = 1.f / l0r;
    const float inv1 = 1.f / l1r;
    const int b = bh >> 4;
    const int h = bh & 15;
    const int t0 = qt*128 + wid*16 + (lane >> 2);
#pragma unroll
    for (int nt = 0; nt < 8; nt++) {
        const int d = nt*8 + (lane & 3)*2;
#pragma unroll
        for (int half = 0; half < 2; half++) {
            const int t = t0 + half*8;
            const float inv = half ? inv1 : inv0;
            const uint32_t hv = pack_h2(o[nt][half*2+0] * inv, o[nt][half*2+1] * inv);
            *(uint32_t*)&g_a16[((size_t)(b*SEQ + t)) * EMB + h*HDIM + d] = hv;
        }
    }
}

// ---------------------------------------------------------------------------
extern "C" void kernel_launch(void* const* d_in, const int* in_sizes, int n_in,
                              void* d_out, int out_size)
{
    const float* x   = (const float*)d_in[0];
    const float* W_q = (const float*)d_in[1];
    const float* b_q = (const float*)d_in[2];
    const float* W_k = (const float*)d_in[3];
    const float* b_k = (const float*)d_in[4];
    const float* W_v = (const float*)d_in[5];
    const float* b_v = (const float*)d_in[6];
    const float* W_o = (const float*)d_in[7];
    const float* b_o = (const float*)d_in[8];
    float* out = (float*)d_out;

    static bool attr_set = false;
    if (!attr_set) {
        cudaFuncSetAttribute(attn_hmma_kernel,
                             cudaFuncAttributeMaxDynamicSharedMemorySize, ATTN_SMEM);
        cudaFuncSetAttribute(qkv_hgemm_kernel,
                             cudaFuncAttributeMaxDynamicSharedMemorySize, GSMEM_BYTES);
        cudaFuncSetAttribute(proj_hgemm_kernel,
                             cudaFuncAttributeMaxDynamicSharedMemorySize, GSMEM_BYTES);
        attr_set = true;
    }

    // 1) fused fp16 conversion (x + 4 weights, one launch)
    convert_all_kernel<<<(CVT_TOTAL + 255) / 256, 256>>>(x, W_q, W_k, W_v, W_o);

    // 2) QKV projections (writes fp16 q/k and transposed v)
    dim3 gqkv(MROWS/128, EMB/128, 3);
    qkv_hgemm_kernel<<<gqkv, 256, GSMEM_BYTES>>>(b_q, b_k, b_v);

    // 3) HMMA flash attention (writes fp16 attention output)
    dim3 gattn(SEQ/128, BATCH*HEADS);
    attn_hmma_kernel<<<gattn, 256, ATTN_SMEM>>>();

    // 4) output projection
    dim3 gproj(MROWS/128, EMB/128);
    proj_hgemm_kernel<<<gproj, 256, GSMEM_BYTES>>>(b_o, out);
}

// round 8
// speedup vs baseline: 6.7694x; 1.1111x over previous
#include <cuda_runtime.h>
#include <cuda_bf16.h>
#include <cuda_fp16.h>
#include <cstdint>
#include <cmath>

// Problem constants
#define BATCH 2
#define SEQ   2048
#define EMB   1024
#define HEADS 16
#define HDIM  64
#define MROWS (BATCH*SEQ)   // 4096

// Scratch (device globals; no allocation allowed)
__device__ __half g_x16[MROWS*EMB];              // x as fp16 (B*T, C)
__device__ __half g_w16[4*EMB*EMB];              // Wq,Wk,Wv,Wo as fp16
__device__ __half g_q16[BATCH*HEADS*SEQ*HDIM];   // (B,H,T,D), pre-scaled by 0.125
__device__ __half g_k16[BATCH*HEADS*SEQ*HDIM];   // (B,H,T,D)
__device__ __half g_v16[BATCH*HEADS*SEQ*HDIM];   // (B,H,D,T)  transposed!
__device__ __half g_a16[MROWS*EMB];              // attention out (B,T,C)

// ---------------------------------------------------------------------------
// PTX helpers (family-level: sm_80+ instructions only)
// ---------------------------------------------------------------------------
__device__ __forceinline__ uint32_t smem_u32(const void* p) {
    uint32_t a;
    asm("{ .reg .u64 t; cvta.to.shared.u64 t, %1; cvt.u32.u64 %0, t; }" : "=r"(a) : "l"(p));
    return a;
}
__device__ __forceinline__ void cp_async16(uint32_t dst, const void* src) {
    asm volatile("cp.async.cg.shared.global [%0], [%1], 16;" :: "r"(dst), "l"(src));
}
__device__ __forceinline__ void cp_commit() {
    asm volatile("cp.async.commit_group;" ::: "memory");
}
template<int N>
__device__ __forceinline__ void cp_wait() {
    asm volatile("cp.async.wait_group %0;" :: "n"(N) : "memory");
}
__device__ __forceinline__ void ldsm_x4(uint32_t* r, uint32_t addr) {
    asm volatile("ldmatrix.sync.aligned.m8n8.x4.shared.b16 {%0,%1,%2,%3}, [%4];"
                 : "=r"(r[0]), "=r"(r[1]), "=r"(r[2]), "=r"(r[3]) : "r"(addr));
}
__device__ __forceinline__ void mma16816h(float* c, const uint32_t* a, const uint32_t* b) {
    asm volatile(
        "mma.sync.aligned.m16n8k16.row.col.f32.f16.f16.f32 "
        "{%0,%1,%2,%3}, {%4,%5,%6,%7}, {%8,%9}, {%0,%1,%2,%3};"
        : "+f"(c[0]), "+f"(c[1]), "+f"(c[2]), "+f"(c[3])
        : "r"(a[0]), "r"(a[1]), "r"(a[2]), "r"(a[3]), "r"(b[0]), "r"(b[1]));
}
// pack two fp32 -> f16x2 (lo in low half)
__device__ __forceinline__ uint32_t pack_h2(float lo, float hi) {
    uint32_t r;
    asm("cvt.rn.f16x2.f32 %0, %1, %2;" : "=r"(r) : "f"(hi), "f"(lo));
    return r;
}
// Swizzle for exact 128B rows (64 fp16). row any, ch 0..7 (16B chunks).
__device__ __forceinline__ uint32_t sw128(int row, int ch) {
    return (uint32_t)(row * 128 + ((ch ^ (row & 7)) * 16));
}

// ---------------------------------------------------------------------------
// Fused fp32 -> fp16 convert: x (1M float4) then Wq,Wk,Wv,Wo (262144 each)
// ---------------------------------------------------------------------------
#define XN4 (MROWS*EMB/4)     // 1048576
#define WN4 (EMB*EMB/4)       // 262144
#define CVT_TOTAL (XN4 + 4*WN4)

__global__ void __launch_bounds__(256) convert_all_kernel(
    const float* __restrict__ x,
    const float* __restrict__ Wq, const float* __restrict__ Wk,
    const float* __restrict__ Wv, const float* __restrict__ Wo)
{
    const int i = blockIdx.x * blockDim.x + threadIdx.x;
    if (i >= CVT_TOTAL) return;
    const float* src;
    uint2* dst;
    int off;
    if (i < XN4) {
        src = x; dst = (uint2*)g_x16; off = i;
    } else {
        const int j = i - XN4;
        const int w = j >> 18;          // / WN4
        off = j & (WN4 - 1);
        src = (w == 0) ? Wq : (w == 1) ? Wk : (w == 2) ? Wv : Wo;
        dst = (uint2*)(g_w16 + (size_t)w * EMB * EMB);
    }
    float4 v = ((const float4*)src)[off];
    uint2 r;
    r.x = pack_h2(v.x, v.y);
    r.y = pack_h2(v.z, v.w);
    dst[off] = r;
}

// ---------------------------------------------------------------------------
// fp16 HMMA GEMM: out[m][n] = sum_k A[m][k]*W[n][k] + bias[n].
// CTA: 128(M) x 64(N) tile, 256 threads, 8 warps (4x2), warp tile 32x32.
// BK=64, SW128 swizzled smem, 3 stages x 24KB = 72KB -> up to 3 CTAs/SM.
// Single __syncthreads per chunk (load issued post-sync, 3-stage safe).
// MODE: 0 = fp32 row-major out; 1 = Q fp16 scaled (B,H,T,D);
//       2 = K fp16 (B,H,T,D);   3 = V fp16 transposed (B,H,D,T)
// ---------------------------------------------------------------------------
#define BK 64
#define A_TILE_B (128*128)           // 16 KB (128 rows x 64 fp16)
#define B_TILE_B (64*128)            // 8 KB
#define STAGE_B (A_TILE_B + B_TILE_B)// 24 KB
#define STAGES 3
#define NCH (EMB/BK)                 // 16
#define GSMEM_BYTES (STAGES*STAGE_B) // 73728

template<int MODE>
__device__ __forceinline__ void hgemm_body(
    const __half* __restrict__ A, const __half* __restrict__ B,
    const float* __restrict__ bias, void* __restrict__ dst)
{
    extern __shared__ __half smb[];
    const uint32_t sm0 = smem_u32(smb);

    const int tid  = threadIdx.x;
    const int wid  = tid >> 5;
    const int lane = tid & 31;
    const int m0 = blockIdx.x * 128;
    const int n0 = blockIdx.y * 64;
    const int warp_m = (wid >> 1) * 32;
    const int warp_n = (wid & 1) * 32;

    const __half* asrc = A + (size_t)m0 * EMB;
    const __half* bsrc = B + (size_t)n0 * EMB;

    // A: 128 rows x 8 chunks (4/thread); B: 64 rows x 8 chunks (2/thread)
    auto load_chunk = [&](int stage, int kc) {
        const uint32_t sb = sm0 + (uint32_t)stage * STAGE_B;
#pragma unroll
        for (int e = 0; e < 4; e++) {
            const int idx = tid * 4 + e;      // 0..1023
            const int row = idx >> 3;
            const int ch  = idx & 7;
            cp_async16(sb + sw128(row, ch),
                       asrc + (size_t)row * EMB + kc * BK + ch * 8);
        }
#pragma unroll
        for (int e = 0; e < 2; e++) {
            const int idx = tid * 2 + e;      // 0..511
            const int row = idx >> 3;
            const int ch  = idx & 7;
            cp_async16(sb + A_TILE_B + sw128(row, ch),
                       bsrc + (size_t)row * EMB + kc * BK + ch * 8);
        }
        cp_commit();
    };

    float c[2][4][4];
#pragma unroll
    for (int mt = 0; mt < 2; mt++)
#pragma unroll
        for (int nt = 0; nt < 4; nt++)
#pragma unroll
            for (int e = 0; e < 4; e++) c[mt][nt][e] = 0.f;

    load_chunk(0, 0);
    load_chunk(1, 1);

    const int lr = lane & 15;
    const int lc = lane >> 4;

    for (int i = 0; i < NCH; i++) {
        if (i < NCH - 1) cp_wait<1>(); else cp_wait<0>();
        __syncthreads();
        if (i + 2 < NCH) load_chunk((i + 2) % STAGES, i + 2);

        const uint32_t ab = sm0 + (uint32_t)(i % STAGES) * STAGE_B;
        const uint32_t bb = ab + A_TILE_B;

#pragma unroll
        for (int kk = 0; kk < 4; kk++) {
            const int ch = kk * 2 + lc;
            uint32_t a[2][4];
#pragma unroll
            for (int mt = 0; mt < 2; mt++)
                ldsm_x4(a[mt], ab + sw128(warp_m + mt * 16 + lr, ch));
#pragma unroll
            for (int nt2 = 0; nt2 < 2; nt2++) {
                uint32_t br[4];
                ldsm_x4(br, bb + sw128(warp_n + nt2 * 16 + lr, ch));
                uint32_t b0[2] = {br[0], br[2]};
                uint32_t b1[2] = {br[1], br[3]};
#pragma unroll
                for (int mt = 0; mt < 2; mt++) {
                    mma16816h(c[mt][2*nt2],   a[mt], b0);
                    mma16816h(c[mt][2*nt2+1], a[mt], b1);
                }
            }
        }
    }

    // --- epilogue
#pragma unroll
    for (int mt = 0; mt < 2; mt++) {
#pragma unroll
        for (int nt = 0; nt < 4; nt++) {
            const int n = n0 + warp_n + nt * 8 + (lane & 3) * 2;
            const float2 bb2 = *(const float2*)&bias[n];
#pragma unroll
            for (int half = 0; half < 2; half++) {
                const int m = m0 + warp_m + mt * 16 + (lane >> 2) + half * 8;
                float rx = c[mt][nt][half*2+0] + bb2.x;
                float ry = c[mt][nt][half*2+1] + bb2.y;
                if (MODE == 0) {
                    float2 r; r.x = rx; r.y = ry;
                    *(float2*)((float*)dst + (size_t)m * EMB + n) = r;
                } else {
                    const int bh = ((m >> 11) << 4) + (n >> 6);  // b*16 + h
                    const int t  = m & (SEQ - 1);
                    const int d  = n & 63;
                    if (MODE == 1) {
                        __half2 hv;
                        hv.x = __float2half_rn(rx * 0.125f);
                        hv.y = __float2half_rn(ry * 0.125f);
                        *(__half2*)((__half*)dst + ((size_t)bh * SEQ + t) * HDIM + d) = hv;
                    } else if (MODE == 2) {
                        __half2 hv;
                        hv.x = __float2half_rn(rx);
                        hv.y = __float2half_rn(ry);
                        *(__half2*)((__half*)dst + ((size_t)bh * SEQ + t) * HDIM + d) = hv;
                    } else {
                        __half* p = (__half*)dst + ((size_t)bh * HDIM + d) * SEQ + t;
                        p[0]   = __float2half_rn(rx);
                        p[SEQ] = __float2half_rn(ry);
                    }
                }
            }
        }
    }
}

__global__ void __launch_bounds__(256, 3) qkv_hgemm_kernel(
    const float* __restrict__ bq, const float* __restrict__ bk, const float* __restrict__ bv)
{
    const int z = blockIdx.z;
    if (z == 0)
        hgemm_body<1>(g_x16, g_w16, bq, g_q16);
    else if (z == 1)
        hgemm_body<2>(g_x16, g_w16 + (size_t)EMB*EMB, bk, g_k16);
    else
        hgemm_body<3>(g_x16, g_w16 + (size_t)2*EMB*EMB, bv, g_v16);
}

__global__ void __launch_bounds__(256, 3) proj_hgemm_kernel(
    const float* __restrict__ bo, float* __restrict__ out)
{
    hgemm_body<0>(g_a16, g_w16 + (size_t)3*EMB*EMB, bo, out);
}

// ---------------------------------------------------------------------------
// HMMA causal flash attention, all-fp16 operands, fp32 accum.
// CTA: 128 queries x one (b,h). 8 warps, each owns 16 query rows.
// KV tiles of 64, 3-stage cp.async ring, single sync per iteration.
// smem: Q 16K + 3 x 16K = 64K -> 2 CTAs/SM.
// Grid: (bh, qt-reversed) so the heaviest CTAs launch in wave 1.
// ---------------------------------------------------------------------------
#define Q_BYTES (128*128)            // 16384
#define KV_STAGE_BYTES (2*64*128)    // K + V per stage = 16384
#define KV_STAGES 3
#define ATTN_SMEM (Q_BYTES + KV_STAGES*KV_STAGE_BYTES)   // 65536

__global__ void __launch_bounds__(256, 2) attn_hmma_kernel()
{
    extern __shared__ char smc[];
    const uint32_t sm0 = smem_u32(smc);

    const int tid  = threadIdx.x;
    const int wid  = tid >> 5;
    const int lane = tid & 31;
    const int bh = blockIdx.x;
    const int qt = (gridDim.y - 1) - blockIdx.y;   // heaviest first

    const __half* qg = g_q16 + (size_t)bh * SEQ * HDIM;   // [t][d]
    const __half* kg = g_k16 + (size_t)bh * SEQ * HDIM;   // [t][d]
    const __half* vg = g_v16 + (size_t)bh * HDIM * SEQ;   // [d][t]

    // ---- issue Q tile load: 128 rows x 8 chunks of 16B (group 1)
#pragma unroll
    for (int e = 0; e < 4; e++) {
        const int idx = tid * 4 + e;        // 0..1023
        const int row = idx >> 3;
        const int ch  = idx & 7;
        cp_async16(sm0 + sw128(row, ch),
                   qg + ((size_t)qt * 128 + row) * HDIM + ch * 8);
    }
    cp_commit();

    auto load_kv = [&](int stage, int kt) {
        const uint32_t sb = sm0 + Q_BYTES + (uint32_t)stage * KV_STAGE_BYTES;
#pragma unroll
        for (int e = 0; e < 2; e++) {
            const int idx = tid * 2 + e;    // 0..511
            const int row = idx >> 3;
            const int ch  = idx & 7;
            cp_async16(sb + sw128(row, ch),
                       kg + ((size_t)kt * 64 + row) * HDIM + ch * 8);
            cp_async16(sb + 64*128 + sw128(row, ch),
                       vg + (size_t)row * SEQ + kt * 64 + ch * 8);
        }
        cp_commit();
    };

    const int nkv = 2 * qt + 2;
    load_kv(0, 0);                 // group 2
    if (nkv > 1) load_kv(1, 1);    // group 3

    // Q ready when <=2 groups pending
    cp_wait<2>();
    __syncthreads();

    const int lr = lane & 15;
    const int lc = lane >> 4;

    // ---- Q fragments (per warp, rows wid*16..+15), 4 k-steps
    uint32_t aq[4][4];
#pragma unroll
    for (int kk = 0; kk < 4; kk++)
        ldsm_x4(aq[kk], sm0 + sw128(wid*16 + lr, kk*2 + lc));

    float o[8][4];
#pragma unroll
    for (int nt = 0; nt < 8; nt++)
#pragma unroll
        for (int e = 0; e < 4; e++) o[nt][e] = 0.f;
    float m0r = -INFINITY, m1r = -INFINITY, l0r = 0.f, l1r = 0.f;

    const float LOG2E = 1.4426950408889634f;
    const int rbase = qt*128 + wid*16 + (lane >> 2);

    for (int kt = 0; kt < nkv; kt++) {
        if (kt < nkv - 1) cp_wait<1>(); else cp_wait<0>();
        __syncthreads();
        if (kt + 2 < nkv) load_kv((kt + 2) % KV_STAGES, kt + 2);

        const uint32_t kb = sm0 + Q_BYTES + (uint32_t)(kt % KV_STAGES) * KV_STAGE_BYTES;
        const uint32_t vb = kb + 64*128;

        // ---- S = Q K^T
        float s[8][4];
#pragma unroll
        for (int nt = 0; nt < 8; nt++)
#pragma unroll
            for (int e = 0; e < 4; e++) s[nt][e] = 0.f;

#pragma unroll
        for (int kk = 0; kk < 4; kk++) {
#pragma unroll
            for (int nt2 = 0; nt2 < 4; nt2++) {
                uint32_t br[4];
                ldsm_x4(br, kb + sw128(nt2*16 + lr, kk*2 + lc));
                uint32_t b0[2] = {br[0], br[2]};
                uint32_t b1[2] = {br[1], br[3]};
                mma16816h(s[2*nt2],   aq[kk], b0);
                mma16816h(s[2*nt2+1], aq[kk], b1);
            }
        }

        // ---- causal mask (diagonal region only)
        if (kt >= 2*qt) {
#pragma unroll
            for (int nt = 0; nt < 8; nt++) {
                const int col = kt*64 + nt*8 + (lane & 3)*2;
#pragma unroll
                for (int e = 0; e < 4; e++) {
                    const int cc = col + (e & 1);
                    const int rr = rbase + (e >> 1)*8;
                    if (cc > rr) s[nt][e] = -1e30f;
                }
            }
        }

        // ---- online softmax (rows r0 = lane>>2, r1 = r0+8; quad-lane reduce)
        float mx0 = -INFINITY, mx1 = -INFINITY;
#pragma unroll
        for (int nt = 0; nt < 8; nt++) {
            mx0 = fmaxf(mx0, fmaxf(s[nt][0], s[nt][1]));
            mx1 = fmaxf(mx1, fmaxf(s[nt][2], s[nt][3]));
        }
        mx0 = fmaxf(mx0, __shfl_xor_sync(0xffffffffu, mx0, 1));
        mx0 = fmaxf(mx0, __shfl_xor_sync(0xffffffffu, mx0, 2));
        mx1 = fmaxf(mx1, __shfl_xor_sync(0xffffffffu, mx1, 1));
        mx1 = fmaxf(mx1, __shfl_xor_sync(0xffffffffu, mx1, 2));
        const float mn0 = fmaxf(m0r, mx0);
        const float mn1 = fmaxf(m1r, mx1);
        const float a0 = exp2f((m0r - mn0) * LOG2E);
        const float a1 = exp2f((m1r - mn1) * LOG2E);
        m0r = mn0; m1r = mn1;

        float rs0 = 0.f, rs1 = 0.f;
#pragma unroll
        for (int nt = 0; nt < 8; nt++) {
            float p0 = exp2f((s[nt][0] - mn0) * LOG2E);
            float p1 = exp2f((s[nt][1] - mn0) * LOG2E);
            float p2 = exp2f((s[nt][2] - mn1) * LOG2E);
            float p3 = exp2f((s[nt][3] - mn1) * LOG2E);
            s[nt][0] = p0; s[nt][1] = p1; s[nt][2] = p2; s[nt][3] = p3;
            rs0 += p0 + p1; rs1 += p2 + p3;
        }
        rs0 += __shfl_xor_sync(0xffffffffu, rs0, 1);
        rs0 += __shfl_xor_sync(0xffffffffu, rs0, 2);
        rs1 += __shfl_xor_sync(0xffffffffu, rs1, 1);
        rs1 += __shfl_xor_sync(0xffffffffu, rs1, 2);
        l0r = l0r * a0 + rs0;
        l1r = l1r * a1 + rs1;

#pragma unroll
        for (int nt = 0; nt < 8; nt++) {
            o[nt][0] *= a0; o[nt][1] *= a0;
            o[nt][2] *= a1; o[nt][3] *= a1;
        }

        // ---- P fragments (C-frag -> A-frag identity)
        uint32_t pf[4][4];
#pragma unroll
        for (int kk = 0; kk < 4; kk++) {
            pf[kk][0] = pack_h2(s[2*kk][0],   s[2*kk][1]);
            pf[kk][1] = pack_h2(s[2*kk][2],   s[2*kk][3]);
            pf[kk][2] = pack_h2(s[2*kk+1][0], s[2*kk+1][1]);
            pf[kk][3] = pack_h2(s[2*kk+1][2], s[2*kk+1][3]);
        }

        // ---- O += P V   (V^T in smem: [d][kv])
#pragma unroll
        for (int kk = 0; kk < 4; kk++) {
#pragma unroll
            for (int nt2 = 0; nt2 < 4; nt2++) {
                uint32_t br[4];
                ldsm_x4(br, vb + sw128(nt2*16 + lr, kk*2 + lc));
                uint32_t b0[2] = {br[0], br[2]};
                uint32_t b1[2] = {br[1], br[3]};
                mma16816h(o[2*nt2],   pf[kk], b0);
                mma16816h(o[2*nt2+1], pf[kk], b1);
            }
        }
    }

    // ---- finalize: write fp16 into (B,T,C)
    const float inv0 = 1.f / l0r;
    const float inv1 = 1.f / l1r;
    const int b = bh >> 4;
    const int h = bh & 15;
    const int t0 = qt*128 + wid*16 + (lane >> 2);
#pragma unroll
    for (int nt = 0; nt < 8; nt++) {
        const int d = nt*8 + (lane & 3)*2;
#pragma unroll
        for (int half = 0; half < 2; half++) {
            const int t = t0 + half*8;
            const float inv = half ? inv1 : inv0;
            const uint32_t hv = pack_h2(o[nt][half*2+0] * inv, o[nt][half*2+1] * inv);
            *(uint32_t*)&g_a16[((size_t)(b*SEQ + t)) * EMB + h*HDIM + d] = hv;
        }
    }
}

// ---------------------------------------------------------------------------
extern "C" void kernel_launch(void* const* d_in, const int* in_sizes, int n_in,
                              void* d_out, int out_size)
{
    const float* x   = (const float*)d_in[0];
    const float* W_q = (const float*)d_in[1];
    const float* b_q = (const float*)d_in[2];
    const float* W_k = (const float*)d_in[3];
    const float* b_k = (const float*)d_in[4];
    const float* W_v = (const float*)d_in[5];
    const float* b_v = (const float*)d_in[6];
    const float* W_o = (const float*)d_in[7];
    const float* b_o = (const float*)d_in[8];
    float* out = (float*)d_out;

    static bool attr_set = false;
    if (!attr_set) {
        cudaFuncSetAttribute(attn_hmma_kernel,
                             cudaFuncAttributeMaxDynamicSharedMemorySize, ATTN_SMEM);
        cudaFuncSetAttribute(qkv_hgemm_kernel,
                             cudaFuncAttributeMaxDynamicSharedMemorySize, GSMEM_BYTES);
        cudaFuncSetAttribute(proj_hgemm_kernel,
                             cudaFuncAttributeMaxDynamicSharedMemorySize, GSMEM_BYTES);
        attr_set = true;
    }

    // 1) fused fp16 conversion (x + 4 weights, one launch)
    convert_all_kernel<<<(CVT_TOTAL + 255) / 256, 256>>>(x, W_q, W_k, W_v, W_o);

    // 2) QKV projections (writes fp16 q/k and transposed v)
    dim3 gqkv(MROWS/128, EMB/64, 3);
    qkv_hgemm_kernel<<<gqkv, 256, GSMEM_BYTES>>>(b_q, b_k, b_v);

    // 3) HMMA flash attention (writes fp16 attention output)
    dim3 gattn(BATCH*HEADS, SEQ/128);
    attn_hmma_kernel<<<gattn, 256, ATTN_SMEM>>>();

    // 4) output projection
    dim3 gproj(MROWS/128, EMB/64);
    proj_hgemm_kernel<<<gproj, 256, GSMEM_BYTES>>>(b_o, out);
}